// round 13
// baseline (speedup 1.0000x reference)
#include <cuda_runtime.h>
#include <cstdint>

#define Bdim 16
#define Sdim 256
#define Hdim 768
#define Ddim 64
#define NSLOT 128
#define H4 (Hdim / 4)

// Scratch (device globals; no allocation allowed)
__device__ __align__(16) float g_u1[Hdim];
__device__ __align__(16) float g_u2[Hdim];
__device__ float g_c[2];
__device__ __align__(16) float g_t2[Bdim * Sdim];
__device__ __align__(16) float g_attn[NSLOT * Sdim];
__device__ __align__(16) float g_X1[2 * NSLOT * Hdim];       // rows 0-127: v (atomic); 128-255: bert_next
__device__ __align__(16) float g_X2[NSLOT * (Hdim + Ddim)];  // [agg_z(atomic) | agg_d]
__device__ __align__(16) float g_X3[NSLOT * (2 * Hdim)];     // [nrep(atomic) | zrow(atomic)]
__device__ __align__(16) float g_T[NSLOT * Hdim];            // temp (atomic)
__device__ int g_valid[NSLOT];
__device__ int g_rowi[NSLOT];

#define ATT_SMEM_FLOATS (68 * 256 + 256 + 256 + 32 + 1024)

__global__ void __launch_bounds__(1024) k_att(const float*, const float*,
                                              const int*, const int*, const int*,
                                              const float*, const float*);

static cudaStream_t g_s3;
static cudaEvent_t g_evFork, g_evCopy;
namespace {
struct HostInit {
  HostInit() {
    cudaStreamCreateWithFlags(&g_s3, cudaStreamNonBlocking);
    cudaEventCreateWithFlags(&g_evFork, cudaEventDisableTiming);
    cudaEventCreateWithFlags(&g_evCopy, cudaEventDisableTiming);
    cudaFuncSetAttribute(k_att, cudaFuncAttributeMaxDynamicSharedMemorySize,
                         ATT_SMEM_FLOATS * 4);
  }
};
HostInit g_hostInit;
}  // namespace

__device__ __forceinline__ float warpReduceSum(float v) {
#pragma unroll
  for (int o = 16; o > 0; o >>= 1) v += __shfl_down_sync(0xffffffffu, v, o);
  return v;
}
__device__ __forceinline__ float warpReduceMax(float v) {
#pragma unroll
  for (int o = 16; o > 0; o >>= 1) v = fmaxf(v, __shfl_down_sync(0xffffffffu, v, o));
  return v;
}
__device__ __forceinline__ float blockReduceSum(float v, float* sm) {
  v = warpReduceSum(v);
  int w = threadIdx.x >> 5;
  if ((threadIdx.x & 31) == 0) sm[w] = v;
  __syncthreads();
  if (threadIdx.x < 8) {
    float x = sm[threadIdx.x];
#pragma unroll
    for (int o = 4; o > 0; o >>= 1) x += __shfl_down_sync(0xffu, x, o);
    if (threadIdx.x == 0) sm[0] = x;
  }
  __syncthreads();
  float r = sm[0];
  __syncthreads();
  return r;
}
__device__ __forceinline__ float blockReduceSum32(float v, float* sm) {
  v = warpReduceSum(v);
  int w = threadIdx.x >> 5;
  if ((threadIdx.x & 31) == 0) sm[w] = v;
  __syncthreads();
  if (threadIdx.x < 32) {
    float x = warpReduceSum(sm[threadIdx.x]);
    if (threadIdx.x == 0) sm[0] = x;
  }
  __syncthreads();
  float r = sm[0];
  __syncthreads();
  return r;
}
__device__ __forceinline__ float blockReduceMax32(float v, float* sm) {
  v = warpReduceMax(v);
  int w = threadIdx.x >> 5;
  if ((threadIdx.x & 31) == 0) sm[w] = v;
  __syncthreads();
  if (threadIdx.x < 32) {
    float x = warpReduceMax(sm[threadIdx.x]);
    if (threadIdx.x == 0) sm[0] = x;
  }
  __syncthreads();
  float r = sm[0];
  __syncthreads();
  return r;
}

// ---- packed f32x2 helpers ----
__device__ __forceinline__ unsigned long long splat2(float x) {
  unsigned long long r;
  asm("mov.b64 %0, {%1, %2};" : "=l"(r) : "f"(x), "f"(x));
  return r;
}
__device__ __forceinline__ void ffma2(unsigned long long& a, unsigned long long x,
                                      unsigned long long w) {
  asm("fma.rn.f32x2 %0, %1, %2, %0;" : "+l"(a) : "l"(x), "l"(w));
}
__device__ __forceinline__ float2 u2f(unsigned long long v) {
  float2 f;
  asm("mov.b64 {%0, %1}, %2;" : "=f"(f.x), "=f"(f.y) : "l"(v));
  return f;
}

// ---- cp.async helpers ----
__device__ __forceinline__ unsigned int saddr_of(const void* p) {
  return (unsigned int)__cvta_generic_to_shared(p);
}
__device__ __forceinline__ void cpasync16(unsigned int saddr, const void* g) {
  asm volatile("cp.async.ca.shared.global [%0], [%1], 16;" ::"r"(saddr), "l"(g));
}
__device__ __forceinline__ void cpasync_commit() {
  asm volatile("cp.async.commit_group;" ::: "memory");
}
__device__ __forceinline__ void cpasync_wait1() {
  asm volatile("cp.async.wait_group 1;" ::: "memory");
}
__device__ __forceinline__ void cpasync_wait0() {
  asm volatile("cp.async.wait_group 0;" ::: "memory");
}

__global__ void k_copy(const float4* __restrict__ src, float4* __restrict__ dst) {
  int i = blockIdx.x * 256 + threadIdx.x;
  dst[i] = src[i];
}

// Zero all atomic-accumulation targets. grid 192, block 256 (float4 strided).
__global__ void k_zero() {
  int i = blockIdx.x * 256 + threadIdx.x;
  float4 z = make_float4(0.f, 0.f, 0.f, 0.f);
  if (i < 2 * NSLOT * H4) ((float4*)g_X1)[i] = z;
  if (i < NSLOT * (Hdim + Ddim) / 4) ((float4*)g_X2)[i] = z;
  if (i < NSLOT * 2 * H4) ((float4*)g_X3)[i] = z;
  if (i < NSLOT * H4) ((float4*)g_T)[i] = z;
}

// u1/u2/c. grid 769, block 256.
__global__ void k_pre(const float* __restrict__ Wz, const float* __restrict__ bz,
                      const float* __restrict__ watt) {
  __shared__ float sm[8];
  int h = blockIdx.x, tid = threadIdx.x;
  float a1 = 0.f, a2 = 0.f;
  if (h < Hdim) {
    const float* wr = Wz + (size_t)h * Hdim;
    for (int k = tid; k < Hdim; k += 256) {
      float wv = wr[k];
      a1 = fmaf(wv, watt[k], a1);
      a2 = fmaf(wv, watt[Hdim + k], a2);
    }
  } else {
    for (int k = tid; k < Hdim; k += 256) {
      float bv = bz[k];
      a1 = fmaf(bv, watt[k], a1);
      a2 = fmaf(bv, watt[Hdim + k], a2);
    }
  }
  float r1 = blockReduceSum(a1, sm);
  float r2 = blockReduceSum(a2, sm);
  if (tid == 0) {
    if (h < Hdim) {
      g_u1[h] = r1;
      g_u2[h] = r2;
    } else {
      g_c[0] = r1;
      g_c[1] = r2;
    }
  }
}

// t2[r] = bert_row[r] @ u2 + bz.w2. grid 512, block 256.
__global__ void k_t2d(const float* __restrict__ bert) {
  int r = blockIdx.x * 8 + (threadIdx.x >> 5);
  int lane = threadIdx.x & 31;
  const float4* br = (const float4*)(bert + (size_t)r * Hdim);
  const float4* u24 = (const float4*)g_u2;
  float a = 0.f;
#pragma unroll
  for (int k = lane; k < H4; k += 32) {
    float4 bv = br[k];
    float4 uv = u24[k];
    a = fmaf(bv.x, uv.x, a);
    a = fmaf(bv.y, uv.y, a);
    a = fmaf(bv.z, uv.z, a);
    a = fmaf(bv.w, uv.w, a);
  }
  a = warpReduceSum(a);
  if (lane == 0) g_t2[r] = a + g_c[1];
}

// Attention: smem-staged dta row; logits + softmax + agg_d + bert_next row.
// grid (16,8), block 1024.
__global__ void __launch_bounds__(1024) k_att(
    const float* __restrict__ bert, const float* __restrict__ dta,
    const int* __restrict__ deprel, const int* __restrict__ asp_s,
    const int* __restrict__ asp_e, const float* __restrict__ w_att,
    const float* __restrict__ b_att) {
  extern __shared__ float dyns[];
  float* sD = dyns;
  float* sm_s = dyns + 68 * 256;
  float* sm_p = sm_s + 256;
  float* sm_red = sm_p + 256;
  float* sm_agg = sm_red + 32;

  int b = blockIdx.x, il = blockIdx.y;
  int slot = b * 8 + il;
  int tid = threadIdx.x;

  int start = asp_s[b], endi = asp_e[b];
  int i = start + il;
  bool active = (i <= endi) && (i < Sdim);
  const int* deprow = deprel + (size_t)(b * Sdim + (active ? i : 0)) * Sdim;
  int hasn = 0;
  if (active && tid < Sdim) hasn = (deprow[tid] > 0);
  int any = __syncthreads_or(hasn);
  if (!active || !any) {
    if (tid < Sdim) g_attn[slot * Sdim + tid] = 0.f;
    if (tid == 0) {
      g_valid[slot] = 0;
      g_rowi[slot] = 0;
    }
    return;
  }

  const float4* drow4 = (const float4*)(dta + (size_t)(b * Sdim + i) * Sdim * Ddim);
#pragma unroll
  for (int t = tid; t < 4096; t += 1024) {
    int j = t >> 4, q = t & 15;
    cpasync16(saddr_of(sD + j * 68 + q * 4), drow4 + t);
  }
  cpasync_commit();

  int inext = (i + 1) & (Sdim - 1);
  const float* bi = bert + (size_t)(b * Sdim + inext) * Hdim;

  float a = (tid < Hdim) ? bi[tid] * g_u1[tid] : 0.f;
  float s1 = blockReduceSum32(a, sm_red);
  float base = s1 + g_c[0] + b_att[0];

  // bert_next row -> X1[128+slot] (overlaps with cp.async drain)
  if (tid < H4)
    ((float4*)g_X1)[(NSLOT + slot) * H4 + tid] = ((const float4*)bi)[tid];

  cpasync_wait0();
  __syncthreads();

  {
    int j = tid >> 2, q = tid & 3;
    const float4* dj = (const float4*)(sD + j * 68) + q * 4;
    const float4* w34 = (const float4*)(w_att + 2 * Hdim) + q * 4;
    float acc = 0.f;
#pragma unroll
    for (int k = 0; k < 4; ++k) {
      float4 d = dj[k];
      float4 w = w34[k];
      acc = fmaf(d.x, w.x, acc);
      acc = fmaf(d.y, w.y, acc);
      acc = fmaf(d.z, w.z, acc);
      acc = fmaf(d.w, w.w, acc);
    }
    acc += __shfl_xor_sync(0xffffffffu, acc, 1);
    acc += __shfl_xor_sync(0xffffffffu, acc, 2);
    if (q == 0) {
      float s = base + g_t2[b * Sdim + ((j + 1) & (Sdim - 1))] + acc;
      s = (s >= 0.f) ? s : 0.01f * s;
      if (deprow[j] <= 0) s = -1e9f;
      sm_s[j] = s;
    }
  }
  __syncthreads();

  float sv = (tid < Sdim) ? sm_s[tid] : -1e30f;
  float m = blockReduceMax32(sv, sm_red);
  float e = (tid < Sdim) ? expf(sv - m) : 0.f;
  float sum = blockReduceSum32(e, sm_red);
  if (tid < Sdim) {
    float p = e / sum;
    sm_p[tid] = p;
    g_attn[slot * Sdim + tid] = p;
  }
  __syncthreads();

  {
    int d = tid & 63, part = tid >> 6;
    float ad = 0.f;
    const float* dp = sD + (size_t)(part * 16) * 68 + d;
#pragma unroll
    for (int jj = 0; jj < 16; ++jj) ad = fmaf(sm_p[part * 16 + jj], dp[jj * 68], ad);
    sm_agg[tid] = ad;
    __syncthreads();
    if (tid < Ddim) {
      float t = 0.f;
#pragma unroll
      for (int p = 0; p < 16; ++p) t += sm_agg[p * 64 + tid];
      g_X2[slot * (Hdim + Ddim) + Hdim + tid] = t;
    }
  }
  if (tid == 0) {
    g_valid[slot] = 1;
    g_rowi[slot] = i;
  }
}

// v partials: atomic accumulate into X1 rows 0..127. grid (128, 8), block 192.
__global__ void __launch_bounds__(192) k_v(const float* __restrict__ bert) {
  int slot = blockIdx.x, g = blockIdx.y;
  int b = slot >> 3;
  int tid = threadIdx.x;
  __shared__ float sp[32];
  if (tid < 32) sp[tid] = g_attn[slot * Sdim + g * 32 + tid];
  __syncthreads();
  const float4* bb4 = (const float4*)(bert + (size_t)b * Sdim * Hdim);
  float4 acc = make_float4(0.f, 0.f, 0.f, 0.f);
#pragma unroll 8
  for (int jj = 0; jj < 32; ++jj) {
    int j = g * 32 + jj;
    float p = sp[jj];
    float4 bv = bb4[(size_t)((j + 1) & (Sdim - 1)) * H4 + tid];
    acc.x = fmaf(p, bv.x, acc.x);
    acc.y = fmaf(p, bv.y, acc.y);
    acc.z = fmaf(p, bv.z, acc.z);
    acc.w = fmaf(p, bv.w, acc.w);
  }
  float* dst = g_X1 + (size_t)slot * Hdim + tid * 4;
  atomicAdd(dst + 0, acc.x);
  atomicAdd(dst + 1, acc.y);
  atomicAdd(dst + 2, acc.z);
  atomicAdd(dst + 3, acc.w);
}

#define FMAK4(C, WV, A0, A1, A2, A3)  \
  do {                                \
    unsigned long long s;             \
    s = splat2(x0.C);                 \
    ffma2(A0##l, s, (WV).x);          \
    ffma2(A0##h, s, (WV).y);          \
    s = splat2(x1.C);                 \
    ffma2(A1##l, s, (WV).x);          \
    ffma2(A1##h, s, (WV).y);          \
    s = splat2(x2.C);                 \
    ffma2(A2##l, s, (WV).x);          \
    ffma2(A2##h, s, (WV).y);          \
    s = splat2(x3.C);                 \
    ffma2(A3##l, s, (WV).x);          \
    ffma2(A3##h, s, (WV).y);          \
  } while (0)

// cp.async smem-staged K-split GEMM with ATOMIC accumulation into the final
// destination (z==0 block adds bias). Block 256, tile 64 cols x 128 rows.
// MODE 0: X1(256xH)@Wz -> agg_z (X2, rows<128, +bz) / zrow (X3 cols 768.., +bz)
// MODE 1: X2(128x832)@Wf -> nrep (X3 cols 0..767)
// MODE 2: X3(128x1536)@Wh -> g_T
template <int KS, int LDX, int NIT, int MODE>
__global__ void __launch_bounds__(256) k_sgemm(const float* __restrict__ X,
                                               const float* __restrict__ W,
                                               const float* __restrict__ bias) {
  static_assert(KS == NIT * 32, "");
  __shared__ __align__(16) float sW[2][32 * 64];
  __shared__ __align__(16) float sX[2][128 * 32];

  int tid = threadIdx.x;
  int ct = tid & 15, rt = tid >> 4;
  int hb = blockIdx.x * 64;
  int rb = blockIdx.y * 128;
  int z = blockIdx.z;

  const float* Wg = W + (size_t)z * KS * Hdim + hb;
  const float* Xg = X + (size_t)rb * LDX + (size_t)z * KS;

  int wi = tid >> 4, wj = (tid & 15) * 4;
  int xi = tid >> 3, xj = (tid & 7) * 4;
  unsigned int sw0 = saddr_of(&sW[0][0]);
  unsigned int sx0 = saddr_of(&sX[0][0]);

#define LOAD_STAGE(stage, buf)                                                  \
  do {                                                                          \
    int k0 = (stage) * 32;                                                      \
    unsigned int swb = sw0 + (buf) * (32 * 64 * 4);                             \
    unsigned int sxb = sx0 + (buf) * (128 * 32 * 4);                            \
    cpasync16(swb + (wi * 64 + wj) * 4, Wg + (size_t)(k0 + wi) * Hdim + wj);    \
    cpasync16(swb + ((wi + 16) * 64 + wj) * 4,                                  \
              Wg + (size_t)(k0 + wi + 16) * Hdim + wj);                         \
    cpasync16(sxb + (xi * 32 + xj) * 4, Xg + (size_t)xi * LDX + k0 + xj);       \
    cpasync16(sxb + ((xi + 32) * 32 + xj) * 4,                                  \
              Xg + (size_t)(xi + 32) * LDX + k0 + xj);                          \
    cpasync16(sxb + ((xi + 64) * 32 + xj) * 4,                                  \
              Xg + (size_t)(xi + 64) * LDX + k0 + xj);                          \
    cpasync16(sxb + ((xi + 96) * 32 + xj) * 4,                                  \
              Xg + (size_t)(xi + 96) * LDX + k0 + xj);                          \
    cpasync_commit();                                                           \
  } while (0)

  LOAD_STAGE(0, 0);
  if (NIT > 1) LOAD_STAGE(1, 1);

  unsigned long long a0l = 0, a0h = 0, a1l = 0, a1h = 0;
  unsigned long long a2l = 0, a2h = 0, a3l = 0, a3h = 0;
  unsigned long long a4l = 0, a4h = 0, a5l = 0, a5h = 0;
  unsigned long long a6l = 0, a6h = 0, a7l = 0, a7h = 0;
  int r0 = rt * 8;

#pragma unroll 1
  for (int it = 0; it < NIT; ++it) {
    if (it < NIT - 1)
      cpasync_wait1();
    else
      cpasync_wait0();
    __syncthreads();
    int buf = it & 1;
    const float* xbase = &sX[buf][0];
    const float* wb = &sW[buf][ct * 4];
#pragma unroll
    for (int k4 = 0; k4 < 8; ++k4) {
      ulonglong2 w0 = *(const ulonglong2*)(wb + (k4 * 4 + 0) * 64);
      ulonglong2 w1 = *(const ulonglong2*)(wb + (k4 * 4 + 1) * 64);
      ulonglong2 w2 = *(const ulonglong2*)(wb + (k4 * 4 + 2) * 64);
      ulonglong2 w3 = *(const ulonglong2*)(wb + (k4 * 4 + 3) * 64);
      {
        float4 x0 = *(const float4*)(xbase + (r0 + 0) * 32 + k4 * 4);
        float4 x1 = *(const float4*)(xbase + (r0 + 1) * 32 + k4 * 4);
        float4 x2 = *(const float4*)(xbase + (r0 + 2) * 32 + k4 * 4);
        float4 x3 = *(const float4*)(xbase + (r0 + 3) * 32 + k4 * 4);
        FMAK4(x, w0, a0, a1, a2, a3);
        FMAK4(y, w1, a0, a1, a2, a3);
        FMAK4(z, w2, a0, a1, a2, a3);
        FMAK4(w, w3, a0, a1, a2, a3);
      }
      {
        float4 x0 = *(const float4*)(xbase + (r0 + 4) * 32 + k4 * 4);
        float4 x1 = *(const float4*)(xbase + (r0 + 5) * 32 + k4 * 4);
        float4 x2 = *(const float4*)(xbase + (r0 + 6) * 32 + k4 * 4);
        float4 x3 = *(const float4*)(xbase + (r0 + 7) * 32 + k4 * 4);
        FMAK4(x, w0, a4, a5, a6, a7);
        FMAK4(y, w1, a4, a5, a6, a7);
        FMAK4(z, w2, a4, a5, a6, a7);
        FMAK4(w, w3, a4, a5, a6, a7);
      }
    }
    __syncthreads();
    if (it + 2 < NIT) LOAD_STAGE(it + 2, buf);
  }
#undef LOAD_STAGE

  float4 bb = make_float4(0.f, 0.f, 0.f, 0.f);
  if (MODE == 0 && z == 0) bb = *(const float4*)(bias + hb + ct * 4);

  float vals[8][4];
#define UNPACK_ROW(q, A)              \
  {                                   \
    float2 fl = u2f(A##l), fh = u2f(A##h); \
    vals[q][0] = fl.x + bb.x;         \
    vals[q][1] = fl.y + bb.y;         \
    vals[q][2] = fh.x + bb.z;         \
    vals[q][3] = fh.y + bb.w;         \
  }
  UNPACK_ROW(0, a0)
  UNPACK_ROW(1, a1)
  UNPACK_ROW(2, a2)
  UNPACK_ROW(3, a3)
  UNPACK_ROW(4, a4)
  UNPACK_ROW(5, a5)
  UNPACK_ROW(6, a6)
  UNPACK_ROW(7, a7)
#undef UNPACK_ROW

#pragma unroll
  for (int q = 0; q < 8; ++q) {
    int rr = rb + r0 + q;
    float* dst;
    if (MODE == 0) {
      dst = (rr < NSLOT)
                ? g_X2 + (size_t)rr * (Hdim + Ddim) + hb + ct * 4
                : g_X3 + (size_t)(rr - NSLOT) * (2 * Hdim) + Hdim + hb + ct * 4;
    } else if (MODE == 1) {
      dst = g_X3 + (size_t)rr * (2 * Hdim) + hb + ct * 4;
    } else {
      dst = g_T + (size_t)rr * Hdim + hb + ct * 4;
    }
    atomicAdd(dst + 0, vals[q][0]);
    atomicAdd(dst + 1, vals[q][1]);
    atomicAdd(dst + 2, vals[q][2]);
    atomicAdd(dst + 3, vals[q][3]);
  }
}

// Final scatter: g_T valid rows -> out[(i+1)]. grid 128, block 192.
__global__ void __launch_bounds__(192) k_scatter(float* __restrict__ outp) {
  int r = blockIdx.x;
  if (!g_valid[r]) return;
  int h = threadIdx.x * 4;
  float4 v = *(const float4*)(g_T + (size_t)r * Hdim + h);
  int bb = r >> 3;
  int o = (g_rowi[r] + 1) & (Sdim - 1);
  *(float4*)(outp + ((size_t)(bb * Sdim + o)) * Hdim + h) = v;
}

extern "C" void kernel_launch(void* const* d_in, const int* in_sizes, int n_in,
                              void* d_out, int out_size) {
  const float* bert = (const float*)d_in[0];
  const float* dta = (const float*)d_in[1];
  const int* deprel = (const int*)d_in[2];
  const int* asp_s = (const int*)d_in[3];
  const int* asp_e = (const int*)d_in[4];
  const float* Wz = (const float*)d_in[5];
  const float* bz = (const float*)d_in[6];
  const float* watt = (const float*)d_in[7];
  const float* batt = (const float*)d_in[8];
  const float* Wf = (const float*)d_in[9];
  const float* Wh = (const float*)d_in[10];
  float* out = (float*)d_out;

  float* X1;
  float* X2;
  float* X3;
  cudaGetSymbolAddress((void**)&X1, g_X1);
  cudaGetSymbolAddress((void**)&X2, g_X2);
  cudaGetSymbolAddress((void**)&X3, g_X3);

  // Fork: independent bulk copy bert -> out (joined before scatter).
  cudaEventRecord(g_evFork, 0);
  cudaStreamWaitEvent(g_s3, g_evFork, 0);
  k_copy<<<(Bdim * Sdim * Hdim / 4) / 256, 256, 0, g_s3>>>((const float4*)bert,
                                                           (float4*)out);
  cudaEventRecord(g_evCopy, g_s3);

  // Critical path (9 launches).
  k_zero<<<192, 256>>>();
  k_pre<<<769, 256>>>(Wz, bz, watt);
  k_t2d<<<(Bdim * Sdim) / 8, 256>>>(bert);
  k_att<<<dim3(Bdim, 8), 1024, ATT_SMEM_FLOATS * 4>>>(bert, dta, deprel, asp_s,
                                                      asp_e, watt, batt);
  k_v<<<dim3(NSLOT, 8), 192>>>(bert);
  // gemm0: X1(256 x 768) @ Wz  K=768, z=12, NIT=2 -> atomic agg_z / zrow (+bz)
  k_sgemm<64, Hdim, 2, 0><<<dim3(12, 2, 12), 256>>>(X1, Wz, bz);
  // gemm1: X2(128 x 832) @ Wf  K=832, z=13, NIT=2 -> atomic nrep
  k_sgemm<64, Hdim + Ddim, 2, 1><<<dim3(12, 1, 13), 256>>>(X2, Wf, nullptr);
  // gemm2: X3(128 x 1536) @ Wh  K=1536, z=24, NIT=2 -> atomic g_T
  k_sgemm<64, 2 * Hdim, 2, 2><<<dim3(12, 1, 24), 256>>>(X3, Wh, nullptr);
  // Join copy, then scatter.
  cudaStreamWaitEvent(0, g_evCopy, 0);
  k_scatter<<<NSLOT, 192>>>(out);
}

// round 14
// speedup vs baseline: 1.1320x; 1.1320x over previous
#include <cuda_runtime.h>
#include <cstdint>

#define Bdim 16
#define Sdim 256
#define Hdim 768
#define Ddim 64
#define NSLOT 128
#define H4 (Hdim / 4)

// Partial-sum row offsets inside g_P (rows of 768 floats)
#define P0_OFF 0      // gemm0 partials (12 x 256)
#define P1_OFF 3072   // gemm1 partials (13 x 128)
#define P2_OFF 4736   // gemm2 partials (24 x 128)
#define P_ROWS 7808

// Scratch (device globals; no allocation allowed)
__device__ __align__(16) float g_u1[Hdim];
__device__ __align__(16) float g_u2[Hdim];
__device__ float g_c[2];
__device__ __align__(16) float g_t2[Bdim * Sdim];
__device__ __align__(16) float g_attn[NSLOT * Sdim];
__device__ __align__(16) float g_X1[2 * NSLOT * Hdim];  // 0-127: v (atomic); 128-255: bert_next
__device__ __align__(16) float g_X2[NSLOT * (Hdim + Ddim)];  // [agg_z | agg_d]
__device__ __align__(16) float g_X3[NSLOT * (2 * Hdim)];     // [nrep | zrow]
__device__ __align__(16) float g_P[(size_t)P_ROWS * Hdim];
__device__ int g_valid[NSLOT];
__device__ int g_rowi[NSLOT];

#define ATT_SMEM_FLOATS (68 * 256 + 256 + 256 + 32 + 1024)

__global__ void __launch_bounds__(1024) k_att(const float*, const float*,
                                              const int*, const int*, const int*,
                                              const float*, const float*);

static cudaStream_t g_s2, g_s3;
static cudaEvent_t g_evFork, g_evCopy, g_evPref;
namespace {
struct HostInit {
  HostInit() {
    cudaStreamCreateWithFlags(&g_s2, cudaStreamNonBlocking);
    cudaStreamCreateWithFlags(&g_s3, cudaStreamNonBlocking);
    cudaEventCreateWithFlags(&g_evFork, cudaEventDisableTiming);
    cudaEventCreateWithFlags(&g_evCopy, cudaEventDisableTiming);
    cudaEventCreateWithFlags(&g_evPref, cudaEventDisableTiming);
    cudaFuncSetAttribute(k_att, cudaFuncAttributeMaxDynamicSharedMemorySize,
                         ATT_SMEM_FLOATS * 4);
  }
};
HostInit g_hostInit;
}  // namespace

__device__ __forceinline__ float warpReduceSum(float v) {
#pragma unroll
  for (int o = 16; o > 0; o >>= 1) v += __shfl_down_sync(0xffffffffu, v, o);
  return v;
}
__device__ __forceinline__ float warpReduceMax(float v) {
#pragma unroll
  for (int o = 16; o > 0; o >>= 1) v = fmaxf(v, __shfl_down_sync(0xffffffffu, v, o));
  return v;
}
__device__ __forceinline__ float blockReduceSum(float v, float* sm) {
  v = warpReduceSum(v);
  int w = threadIdx.x >> 5;
  if ((threadIdx.x & 31) == 0) sm[w] = v;
  __syncthreads();
  if (threadIdx.x < 8) {
    float x = sm[threadIdx.x];
#pragma unroll
    for (int o = 4; o > 0; o >>= 1) x += __shfl_down_sync(0xffu, x, o);
    if (threadIdx.x == 0) sm[0] = x;
  }
  __syncthreads();
  float r = sm[0];
  __syncthreads();
  return r;
}
__device__ __forceinline__ float blockReduceSum32(float v, float* sm) {
  v = warpReduceSum(v);
  int w = threadIdx.x >> 5;
  if ((threadIdx.x & 31) == 0) sm[w] = v;
  __syncthreads();
  if (threadIdx.x < 32) {
    float x = warpReduceSum(sm[threadIdx.x]);
    if (threadIdx.x == 0) sm[0] = x;
  }
  __syncthreads();
  float r = sm[0];
  __syncthreads();
  return r;
}
__device__ __forceinline__ float blockReduceMax32(float v, float* sm) {
  v = warpReduceMax(v);
  int w = threadIdx.x >> 5;
  if ((threadIdx.x & 31) == 0) sm[w] = v;
  __syncthreads();
  if (threadIdx.x < 32) {
    float x = warpReduceMax(sm[threadIdx.x]);
    if (threadIdx.x == 0) sm[0] = x;
  }
  __syncthreads();
  float r = sm[0];
  __syncthreads();
  return r;
}

// ---- packed f32x2 helpers ----
__device__ __forceinline__ unsigned long long splat2(float x) {
  unsigned long long r;
  asm("mov.b64 %0, {%1, %2};" : "=l"(r) : "f"(x), "f"(x));
  return r;
}
__device__ __forceinline__ void ffma2(unsigned long long& a, unsigned long long x,
                                      unsigned long long w) {
  asm("fma.rn.f32x2 %0, %1, %2, %0;" : "+l"(a) : "l"(x), "l"(w));
}
__device__ __forceinline__ float2 u2f(unsigned long long v) {
  float2 f;
  asm("mov.b64 {%0, %1}, %2;" : "=f"(f.x), "=f"(f.y) : "l"(v));
  return f;
}

// ---- cp.async helpers ----
__device__ __forceinline__ unsigned int saddr_of(const void* p) {
  return (unsigned int)__cvta_generic_to_shared(p);
}
__device__ __forceinline__ void cpasync16(unsigned int saddr, const void* g) {
  asm volatile("cp.async.ca.shared.global [%0], [%1], 16;" ::"r"(saddr), "l"(g));
}
__device__ __forceinline__ void cpasync_commit() {
  asm volatile("cp.async.commit_group;" ::: "memory");
}
__device__ __forceinline__ void cpasync_wait1() {
  asm volatile("cp.async.wait_group 1;" ::: "memory");
}
__device__ __forceinline__ void cpasync_wait0() {
  asm volatile("cp.async.wait_group 0;" ::: "memory");
}
__device__ __forceinline__ void prefetchL2(const void* p) {
  asm volatile("prefetch.global.L2 [%0];" ::"l"(p));
}

__global__ void k_copy(const float4* __restrict__ src, float4* __restrict__ dst) {
  int i = blockIdx.x * 256 + threadIdx.x;
  dst[i] = src[i];
}

// L2 prefetch of the dta/deprel rows k_att will stage. grid 128, block 256.
__global__ void __launch_bounds__(256) k_pref(const float* __restrict__ dta,
                                              const int* __restrict__ deprel,
                                              const int* __restrict__ asp_s,
                                              const int* __restrict__ asp_e) {
  int slot = blockIdx.x;
  int b = slot >> 3, il = slot & 7;
  int i = asp_s[b] + il;
  if (i > asp_e[b] || i >= Sdim) return;
  const char* row = (const char*)(dta + (size_t)(b * Sdim + i) * Sdim * Ddim);
  int tid = threadIdx.x;
  // 64KB = 512 lines of 128B; 2 per thread.
  prefetchL2(row + (size_t)tid * 128);
  prefetchL2(row + (size_t)(tid + 256) * 128);
  if (tid < 8)
    prefetchL2((const char*)(deprel + (size_t)(b * Sdim + i) * Sdim) + tid * 128);
}

// u1/u2/c. grid 769, block 256.
__global__ void k_pre(const float* __restrict__ Wz, const float* __restrict__ bz,
                      const float* __restrict__ watt) {
  __shared__ float sm[8];
  int h = blockIdx.x, tid = threadIdx.x;
  float a1 = 0.f, a2 = 0.f;
  if (h < Hdim) {
    const float* wr = Wz + (size_t)h * Hdim;
    for (int k = tid; k < Hdim; k += 256) {
      float wv = wr[k];
      a1 = fmaf(wv, watt[k], a1);
      a2 = fmaf(wv, watt[Hdim + k], a2);
    }
  } else {
    for (int k = tid; k < Hdim; k += 256) {
      float bv = bz[k];
      a1 = fmaf(bv, watt[k], a1);
      a2 = fmaf(bv, watt[Hdim + k], a2);
    }
  }
  float r1 = blockReduceSum(a1, sm);
  float r2 = blockReduceSum(a2, sm);
  if (tid == 0) {
    if (h < Hdim) {
      g_u1[h] = r1;
      g_u2[h] = r2;
    } else {
      g_c[0] = r1;
      g_c[1] = r2;
    }
  }
}

// t2[r] = bert_row[r] @ u2 + bz.w2. grid 512, block 256.
__global__ void k_t2d(const float* __restrict__ bert) {
  int r = blockIdx.x * 8 + (threadIdx.x >> 5);
  int lane = threadIdx.x & 31;
  const float4* br = (const float4*)(bert + (size_t)r * Hdim);
  const float4* u24 = (const float4*)g_u2;
  float a = 0.f;
#pragma unroll
  for (int k = lane; k < H4; k += 32) {
    float4 bv = br[k];
    float4 uv = u24[k];
    a = fmaf(bv.x, uv.x, a);
    a = fmaf(bv.y, uv.y, a);
    a = fmaf(bv.z, uv.z, a);
    a = fmaf(bv.w, uv.w, a);
  }
  a = warpReduceSum(a);
  if (lane == 0) g_t2[r] = a + g_c[1];
}

// Attention: smem-staged dta row; logits + softmax + agg_d; also zeroes the
// X1 v-row (atomic target) and writes the bert_next row. grid (16,8), 1024 thr.
__global__ void __launch_bounds__(1024) k_att(
    const float* __restrict__ bert, const float* __restrict__ dta,
    const int* __restrict__ deprel, const int* __restrict__ asp_s,
    const int* __restrict__ asp_e, const float* __restrict__ w_att,
    const float* __restrict__ b_att) {
  extern __shared__ float dyns[];
  float* sD = dyns;
  float* sm_s = dyns + 68 * 256;
  float* sm_p = sm_s + 256;
  float* sm_red = sm_p + 256;
  float* sm_agg = sm_red + 32;

  int b = blockIdx.x, il = blockIdx.y;
  int slot = b * 8 + il;
  int tid = threadIdx.x;

  int start = asp_s[b], endi = asp_e[b];
  int i = start + il;
  bool active = (i <= endi) && (i < Sdim);
  const int* deprow = deprel + (size_t)(b * Sdim + (active ? i : 0)) * Sdim;
  int hasn = 0;
  if (active && tid < Sdim) hasn = (deprow[tid] > 0);
  int any = __syncthreads_or(hasn);
  if (!active || !any) {
    if (tid < Sdim) g_attn[slot * Sdim + tid] = 0.f;
    if (tid < H4) {
      float4 z = make_float4(0.f, 0.f, 0.f, 0.f);
      ((float4*)g_X1)[slot * H4 + tid] = z;
      ((float4*)g_X1)[(NSLOT + slot) * H4 + tid] = z;
    }
    if (tid < Ddim) g_X2[slot * (Hdim + Ddim) + Hdim + tid] = 0.f;
    if (tid == 0) {
      g_valid[slot] = 0;
      g_rowi[slot] = 0;
    }
    return;
  }

  const float4* drow4 = (const float4*)(dta + (size_t)(b * Sdim + i) * Sdim * Ddim);
#pragma unroll
  for (int t = tid; t < 4096; t += 1024) {
    int j = t >> 4, q = t & 15;
    cpasync16(saddr_of(sD + j * 68 + q * 4), drow4 + t);
  }
  cpasync_commit();

  int inext = (i + 1) & (Sdim - 1);
  const float* bi = bert + (size_t)(b * Sdim + inext) * Hdim;

  float a = (tid < Hdim) ? bi[tid] * g_u1[tid] : 0.f;
  float s1 = blockReduceSum32(a, sm_red);
  float base = s1 + g_c[0] + b_att[0];

  // zero X1 v-row + write bert_next row (overlaps with cp.async drain)
  if (tid < H4) {
    ((float4*)g_X1)[slot * H4 + tid] = make_float4(0.f, 0.f, 0.f, 0.f);
    ((float4*)g_X1)[(NSLOT + slot) * H4 + tid] = ((const float4*)bi)[tid];
  }

  cpasync_wait0();
  __syncthreads();

  {
    int j = tid >> 2, q = tid & 3;
    const float4* dj = (const float4*)(sD + j * 68) + q * 4;
    const float4* w34 = (const float4*)(w_att + 2 * Hdim) + q * 4;
    float acc = 0.f;
#pragma unroll
    for (int k = 0; k < 4; ++k) {
      float4 d = dj[k];
      float4 w = w34[k];
      acc = fmaf(d.x, w.x, acc);
      acc = fmaf(d.y, w.y, acc);
      acc = fmaf(d.z, w.z, acc);
      acc = fmaf(d.w, w.w, acc);
    }
    acc += __shfl_xor_sync(0xffffffffu, acc, 1);
    acc += __shfl_xor_sync(0xffffffffu, acc, 2);
    if (q == 0) {
      float s = base + g_t2[b * Sdim + ((j + 1) & (Sdim - 1))] + acc;
      s = (s >= 0.f) ? s : 0.01f * s;
      if (deprow[j] <= 0) s = -1e9f;
      sm_s[j] = s;
    }
  }
  __syncthreads();

  float sv = (tid < Sdim) ? sm_s[tid] : -1e30f;
  float m = blockReduceMax32(sv, sm_red);
  float e = (tid < Sdim) ? expf(sv - m) : 0.f;
  float sum = blockReduceSum32(e, sm_red);
  if (tid < Sdim) {
    float p = e / sum;
    sm_p[tid] = p;
    g_attn[slot * Sdim + tid] = p;
  }
  __syncthreads();

  {
    int d = tid & 63, part = tid >> 6;
    float ad = 0.f;
    const float* dp = sD + (size_t)(part * 16) * 68 + d;
#pragma unroll
    for (int jj = 0; jj < 16; ++jj) ad = fmaf(sm_p[part * 16 + jj], dp[jj * 68], ad);
    sm_agg[tid] = ad;
    __syncthreads();
    if (tid < Ddim) {
      float t = 0.f;
#pragma unroll
      for (int p = 0; p < 16; ++p) t += sm_agg[p * 64 + tid];
      g_X2[slot * (Hdim + Ddim) + Hdim + tid] = t;
    }
  }
  if (tid == 0) {
    g_valid[slot] = 1;
    g_rowi[slot] = i;
  }
}

// v partials: atomic accumulate straight into X1 rows 0..127 (zeroed by k_att).
// grid (128, 8), block 192.
__global__ void __launch_bounds__(192) k_v(const float* __restrict__ bert) {
  int slot = blockIdx.x, g = blockIdx.y;
  int b = slot >> 3;
  int tid = threadIdx.x;
  __shared__ float sp[32];
  if (tid < 32) sp[tid] = g_attn[slot * Sdim + g * 32 + tid];
  __syncthreads();
  const float4* bb4 = (const float4*)(bert + (size_t)b * Sdim * Hdim);
  float4 acc = make_float4(0.f, 0.f, 0.f, 0.f);
#pragma unroll 8
  for (int jj = 0; jj < 32; ++jj) {
    int j = g * 32 + jj;
    float p = sp[jj];
    float4 bv = bb4[(size_t)((j + 1) & (Sdim - 1)) * H4 + tid];
    acc.x = fmaf(p, bv.x, acc.x);
    acc.y = fmaf(p, bv.y, acc.y);
    acc.z = fmaf(p, bv.z, acc.z);
    acc.w = fmaf(p, bv.w, acc.w);
  }
  float* dst = g_X1 + (size_t)slot * Hdim + tid * 4;
  atomicAdd(dst + 0, acc.x);
  atomicAdd(dst + 1, acc.y);
  atomicAdd(dst + 2, acc.z);
  atomicAdd(dst + 3, acc.w);
}

#define FMAK4(C, WV, A0, A1, A2, A3)  \
  do {                                \
    unsigned long long s;             \
    s = splat2(x0.C);                 \
    ffma2(A0##l, s, (WV).x);          \
    ffma2(A0##h, s, (WV).y);          \
    s = splat2(x1.C);                 \
    ffma2(A1##l, s, (WV).x);          \
    ffma2(A1##h, s, (WV).y);          \
    s = splat2(x2.C);                 \
    ffma2(A2##l, s, (WV).x);          \
    ffma2(A2##h, s, (WV).y);          \
    s = splat2(x3.C);                 \
    ffma2(A3##l, s, (WV).x);          \
    ffma2(A3##h, s, (WV).y);          \
  } while (0)

// cp.async smem-staged K-split partial GEMM, 4 cols x 8 rows/thread, 64x128 tile.
// grid = (12, rows/128, ksplit); z writes partials to P[(z*NROWS + r)*Hdim + h].
template <int KS, int LDX, int NIT, int NROWS>
__global__ void __launch_bounds__(256) k_sgemm(const float* __restrict__ X,
                                               const float* __restrict__ W,
                                               float* __restrict__ P) {
  static_assert(KS == NIT * 32, "");
  __shared__ __align__(16) float sW[2][32 * 64];
  __shared__ __align__(16) float sX[2][128 * 32];

  int tid = threadIdx.x;
  int ct = tid & 15, rt = tid >> 4;
  int hb = blockIdx.x * 64;
  int rb = blockIdx.y * 128;
  int z = blockIdx.z;

  const float* Wg = W + (size_t)z * KS * Hdim + hb;
  const float* Xg = X + (size_t)rb * LDX + (size_t)z * KS;

  int wi = tid >> 4, wj = (tid & 15) * 4;
  int xi = tid >> 3, xj = (tid & 7) * 4;
  unsigned int sw0 = saddr_of(&sW[0][0]);
  unsigned int sx0 = saddr_of(&sX[0][0]);

#define LOAD_STAGE(stage, buf)                                                  \
  do {                                                                          \
    int k0 = (stage) * 32;                                                      \
    unsigned int swb = sw0 + (buf) * (32 * 64 * 4);                             \
    unsigned int sxb = sx0 + (buf) * (128 * 32 * 4);                            \
    cpasync16(swb + (wi * 64 + wj) * 4, Wg + (size_t)(k0 + wi) * Hdim + wj);    \
    cpasync16(swb + ((wi + 16) * 64 + wj) * 4,                                  \
              Wg + (size_t)(k0 + wi + 16) * Hdim + wj);                         \
    cpasync16(sxb + (xi * 32 + xj) * 4, Xg + (size_t)xi * LDX + k0 + xj);       \
    cpasync16(sxb + ((xi + 32) * 32 + xj) * 4,                                  \
              Xg + (size_t)(xi + 32) * LDX + k0 + xj);                          \
    cpasync16(sxb + ((xi + 64) * 32 + xj) * 4,                                  \
              Xg + (size_t)(xi + 64) * LDX + k0 + xj);                          \
    cpasync16(sxb + ((xi + 96) * 32 + xj) * 4,                                  \
              Xg + (size_t)(xi + 96) * LDX + k0 + xj);                          \
    cpasync_commit();                                                           \
  } while (0)

  LOAD_STAGE(0, 0);
  if (NIT > 1) LOAD_STAGE(1, 1);

  unsigned long long a0l = 0, a0h = 0, a1l = 0, a1h = 0;
  unsigned long long a2l = 0, a2h = 0, a3l = 0, a3h = 0;
  unsigned long long a4l = 0, a4h = 0, a5l = 0, a5h = 0;
  unsigned long long a6l = 0, a6h = 0, a7l = 0, a7h = 0;
  int r0 = rt * 8;

#pragma unroll 1
  for (int it = 0; it < NIT; ++it) {
    if (it < NIT - 1)
      cpasync_wait1();
    else
      cpasync_wait0();
    __syncthreads();
    int buf = it & 1;
    const float* xbase = &sX[buf][0];
    const float* wb = &sW[buf][ct * 4];
#pragma unroll
    for (int k4 = 0; k4 < 8; ++k4) {
      ulonglong2 w0 = *(const ulonglong2*)(wb + (k4 * 4 + 0) * 64);
      ulonglong2 w1 = *(const ulonglong2*)(wb + (k4 * 4 + 1) * 64);
      ulonglong2 w2 = *(const ulonglong2*)(wb + (k4 * 4 + 2) * 64);
      ulonglong2 w3 = *(const ulonglong2*)(wb + (k4 * 4 + 3) * 64);
      {
        float4 x0 = *(const float4*)(xbase + (r0 + 0) * 32 + k4 * 4);
        float4 x1 = *(const float4*)(xbase + (r0 + 1) * 32 + k4 * 4);
        float4 x2 = *(const float4*)(xbase + (r0 + 2) * 32 + k4 * 4);
        float4 x3 = *(const float4*)(xbase + (r0 + 3) * 32 + k4 * 4);
        FMAK4(x, w0, a0, a1, a2, a3);
        FMAK4(y, w1, a0, a1, a2, a3);
        FMAK4(z, w2, a0, a1, a2, a3);
        FMAK4(w, w3, a0, a1, a2, a3);
      }
      {
        float4 x0 = *(const float4*)(xbase + (r0 + 4) * 32 + k4 * 4);
        float4 x1 = *(const float4*)(xbase + (r0 + 5) * 32 + k4 * 4);
        float4 x2 = *(const float4*)(xbase + (r0 + 6) * 32 + k4 * 4);
        float4 x3 = *(const float4*)(xbase + (r0 + 7) * 32 + k4 * 4);
        FMAK4(x, w0, a4, a5, a6, a7);
        FMAK4(y, w1, a4, a5, a6, a7);
        FMAK4(z, w2, a4, a5, a6, a7);
        FMAK4(w, w3, a4, a5, a6, a7);
      }
    }
    __syncthreads();
    if (it + 2 < NIT) LOAD_STAGE(it + 2, buf);
  }
#undef LOAD_STAGE

  int r = rb + r0;
  float* pr = P + ((size_t)(z * NROWS + r)) * Hdim + hb + ct * 4;
#define STORE_ROW(q, A)                                                  \
  {                                                                      \
    float2 fl = u2f(A##l), fh = u2f(A##h);                               \
    *(float4*)(pr + (q)*Hdim) = make_float4(fl.x, fl.y, fh.x, fh.y);     \
  }
  STORE_ROW(0, a0)
  STORE_ROW(1, a1)
  STORE_ROW(2, a2)
  STORE_ROW(3, a3)
  STORE_ROW(4, a4)
  STORE_ROW(5, a5)
  STORE_ROW(6, a6)
  STORE_ROW(7, a7)
#undef STORE_ROW
}

// Epilogue: combine NZ K-split partials at OFF and route per MODE. block 192.
// MODE 0: +bias -> agg_z (X2, r<128) / zrow (X3 cols 768..); MODE 1: -> nrep;
// MODE 2: scatter valid rows to out[(i+1)].
template <int NZ, int OFF, int NROWS, int MODE>
__global__ void __launch_bounds__(192) k_epi(const float* __restrict__ bias,
                                             float* __restrict__ outp) {
  int r = blockIdx.x;
  if (MODE == 2 && !g_valid[r]) return;
  int h = threadIdx.x * 4;
  float4 v = make_float4(0.f, 0.f, 0.f, 0.f);
#pragma unroll
  for (int zz = 0; zz < NZ; ++zz) {
    const float4 p =
        *(const float4*)(g_P + (size_t)(OFF + zz * NROWS + r) * Hdim + h);
    v.x += p.x;
    v.y += p.y;
    v.z += p.z;
    v.w += p.w;
  }
  if (MODE == 0) {
    const float4 bb = *(const float4*)(bias + h);
    v.x += bb.x;
    v.y += bb.y;
    v.z += bb.z;
    v.w += bb.w;
    if (r < NSLOT)
      *(float4*)(g_X2 + (size_t)r * (Hdim + Ddim) + h) = v;
    else
      *(float4*)(g_X3 + (size_t)(r - NSLOT) * (2 * Hdim) + Hdim + h) = v;
  } else if (MODE == 1) {
    *(float4*)(g_X3 + (size_t)r * (2 * Hdim) + h) = v;
  } else {
    int bb = r >> 3;
    int o = (g_rowi[r] + 1) & (Sdim - 1);
    *(float4*)(outp + ((size_t)(bb * Sdim + o)) * Hdim + h) = v;
  }
}

extern "C" void kernel_launch(void* const* d_in, const int* in_sizes, int n_in,
                              void* d_out, int out_size) {
  const float* bert = (const float*)d_in[0];
  const float* dta = (const float*)d_in[1];
  const int* deprel = (const int*)d_in[2];
  const int* asp_s = (const int*)d_in[3];
  const int* asp_e = (const int*)d_in[4];
  const float* Wz = (const float*)d_in[5];
  const float* bz = (const float*)d_in[6];
  const float* watt = (const float*)d_in[7];
  const float* batt = (const float*)d_in[8];
  const float* Wf = (const float*)d_in[9];
  const float* Wh = (const float*)d_in[10];
  float* out = (float*)d_out;

  float* P;
  float* X1;
  float* X2;
  float* X3;
  cudaGetSymbolAddress((void**)&P, g_P);
  cudaGetSymbolAddress((void**)&X1, g_X1);
  cudaGetSymbolAddress((void**)&X2, g_X2);
  cudaGetSymbolAddress((void**)&X3, g_X3);

  // Fork: bulk copy on s3; L2 prefetch of dta/deprel rows on s2.
  cudaEventRecord(g_evFork, 0);
  cudaStreamWaitEvent(g_s3, g_evFork, 0);
  cudaStreamWaitEvent(g_s2, g_evFork, 0);
  k_copy<<<(Bdim * Sdim * Hdim / 4) / 256, 256, 0, g_s3>>>((const float4*)bert,
                                                           (float4*)out);
  cudaEventRecord(g_evCopy, g_s3);
  k_pref<<<NSLOT, 256, 0, g_s2>>>(dta, deprel, asp_s, asp_e);
  cudaEventRecord(g_evPref, g_s2);

  // Critical path.
  k_pre<<<769, 256>>>(Wz, bz, watt);
  k_t2d<<<(Bdim * Sdim) / 8, 256>>>(bert);
  k_att<<<dim3(Bdim, 8), 1024, ATT_SMEM_FLOATS * 4>>>(bert, dta, deprel, asp_s,
                                                      asp_e, watt, batt);
  k_v<<<dim3(NSLOT, 8), 192>>>(bert);
  // gemm0: X1(256 x 768) @ Wz   K=768 z=12 -> P0, epi adds bz
  k_sgemm<64, Hdim, 2, 256><<<dim3(12, 2, 12), 256>>>(X1, Wz, P + (size_t)P0_OFF * Hdim);
  k_epi<12, P0_OFF, 256, 0><<<256, 192>>>(bz, nullptr);
  // gemm1: X2(128 x 832) @ Wf   K=832 z=13 -> P1 -> nrep
  k_sgemm<64, Hdim + Ddim, 2, 128><<<dim3(12, 1, 13), 256>>>(X2, Wf,
                                                             P + (size_t)P1_OFF * Hdim);
  k_epi<13, P1_OFF, 128, 1><<<128, 192>>>(nullptr, nullptr);
  // gemm2: X3(128 x 1536) @ Wh  K=1536 z=24 -> P2 -> out scatter
  k_sgemm<64, 2 * Hdim, 2, 128><<<dim3(12, 1, 24), 256>>>(X3, Wh,
                                                          P + (size_t)P2_OFF * Hdim);
  // Join copy + prefetch streams, then scatter.
  cudaStreamWaitEvent(0, g_evCopy, 0);
  cudaStreamWaitEvent(0, g_evPref, 0);
  k_epi<24, P2_OFF, 128, 2><<<128, 192>>>(nullptr, out);
}

// round 15
// speedup vs baseline: 1.2123x; 1.0710x over previous
#include <cuda_runtime.h>
#include <cstdint>

#define Bdim 16
#define Sdim 256
#define Hdim 768
#define Ddim 64
#define NSLOT 128
#define H4 (Hdim / 4)

// Partial-sum row offsets inside g_P (rows of 768 floats)
#define P0_OFF 0      // gemm0 partials (12 x 256)
#define P1_OFF 3072   // gemm1 partials (13 x 128)
#define P2_OFF 4736   // gemm2 partials (24 x 128)
#define P_ROWS 7808

// Scratch (device globals; no allocation allowed)
__device__ __align__(16) float g_u1[Hdim];
__device__ __align__(16) float g_u2[Hdim];
__device__ float g_c[2];
__device__ __align__(16) float g_X1[2 * NSLOT * Hdim];  // 0-127: v; 128-255: bert_next
__device__ __align__(16) float g_X2[NSLOT * (Hdim + Ddim)];  // [agg_z | agg_d]
__device__ __align__(16) float g_X3[NSLOT * (2 * Hdim)];     // [nrep | zrow]
__device__ __align__(16) float g_P[(size_t)P_ROWS * Hdim];
__device__ int g_cnt[NSLOT];
__device__ int g_jl[NSLOT * Sdim];
__device__ float g_pl[NSLOT * Sdim];
__device__ int g_valid[NSLOT];
__device__ int g_rowi[NSLOT];

// k_att dynamic smem (floats): sD(68*256) s(256) p(256) red(32) agg(1024)
// sj(256) st2(256) spc(256) wcnt/base(17 -> pad 32)
#define ATT_SMEM_FLOATS (68 * 256 + 256 + 256 + 32 + 1024 + 256 + 256 + 256 + 32)

__global__ void __launch_bounds__(1024) k_att(const float*, const float*,
                                              const int*, const int*, const int*,
                                              const float*, const float*);

static cudaStream_t g_s2, g_s3;
static cudaEvent_t g_evFork, g_evCopy, g_evPref;
namespace {
struct HostInit {
  HostInit() {
    cudaStreamCreateWithFlags(&g_s2, cudaStreamNonBlocking);
    cudaStreamCreateWithFlags(&g_s3, cudaStreamNonBlocking);
    cudaEventCreateWithFlags(&g_evFork, cudaEventDisableTiming);
    cudaEventCreateWithFlags(&g_evCopy, cudaEventDisableTiming);
    cudaEventCreateWithFlags(&g_evPref, cudaEventDisableTiming);
    cudaFuncSetAttribute(k_att, cudaFuncAttributeMaxDynamicSharedMemorySize,
                         ATT_SMEM_FLOATS * 4);
  }
};
HostInit g_hostInit;
}  // namespace

__device__ __forceinline__ float warpReduceSum(float v) {
#pragma unroll
  for (int o = 16; o > 0; o >>= 1) v += __shfl_down_sync(0xffffffffu, v, o);
  return v;
}
__device__ __forceinline__ float warpReduceMax(float v) {
#pragma unroll
  for (int o = 16; o > 0; o >>= 1) v = fmaxf(v, __shfl_down_sync(0xffffffffu, v, o));
  return v;
}
__device__ __forceinline__ float blockReduceSum(float v, float* sm) {
  v = warpReduceSum(v);
  int w = threadIdx.x >> 5;
  if ((threadIdx.x & 31) == 0) sm[w] = v;
  __syncthreads();
  if (threadIdx.x < 8) {
    float x = sm[threadIdx.x];
#pragma unroll
    for (int o = 4; o > 0; o >>= 1) x += __shfl_down_sync(0xffu, x, o);
    if (threadIdx.x == 0) sm[0] = x;
  }
  __syncthreads();
  float r = sm[0];
  __syncthreads();
  return r;
}
__device__ __forceinline__ float blockReduceSum32(float v, float* sm) {
  v = warpReduceSum(v);
  int w = threadIdx.x >> 5;
  if ((threadIdx.x & 31) == 0) sm[w] = v;
  __syncthreads();
  if (threadIdx.x < 32) {
    float x = warpReduceSum(sm[threadIdx.x]);
    if (threadIdx.x == 0) sm[0] = x;
  }
  __syncthreads();
  float r = sm[0];
  __syncthreads();
  return r;
}
__device__ __forceinline__ float blockReduceMax32(float v, float* sm) {
  v = warpReduceMax(v);
  int w = threadIdx.x >> 5;
  if ((threadIdx.x & 31) == 0) sm[w] = v;
  __syncthreads();
  if (threadIdx.x < 32) {
    float x = warpReduceMax(sm[threadIdx.x]);
    if (threadIdx.x == 0) sm[0] = x;
  }
  __syncthreads();
  float r = sm[0];
  __syncthreads();
  return r;
}

// ---- packed f32x2 helpers ----
__device__ __forceinline__ unsigned long long splat2(float x) {
  unsigned long long r;
  asm("mov.b64 %0, {%1, %2};" : "=l"(r) : "f"(x), "f"(x));
  return r;
}
__device__ __forceinline__ void ffma2(unsigned long long& a, unsigned long long x,
                                      unsigned long long w) {
  asm("fma.rn.f32x2 %0, %1, %2, %0;" : "+l"(a) : "l"(x), "l"(w));
}
__device__ __forceinline__ float2 u2f(unsigned long long v) {
  float2 f;
  asm("mov.b64 {%0, %1}, %2;" : "=f"(f.x), "=f"(f.y) : "l"(v));
  return f;
}

// ---- cp.async helpers ----
__device__ __forceinline__ unsigned int saddr_of(const void* p) {
  return (unsigned int)__cvta_generic_to_shared(p);
}
__device__ __forceinline__ void cpasync16(unsigned int saddr, const void* g) {
  asm volatile("cp.async.ca.shared.global [%0], [%1], 16;" ::"r"(saddr), "l"(g));
}
__device__ __forceinline__ void cpasync_commit() {
  asm volatile("cp.async.commit_group;" ::: "memory");
}
__device__ __forceinline__ void cpasync_wait1() {
  asm volatile("cp.async.wait_group 1;" ::: "memory");
}
__device__ __forceinline__ void cpasync_wait0() {
  asm volatile("cp.async.wait_group 0;" ::: "memory");
}
__device__ __forceinline__ void prefetchL2(const void* p) {
  asm volatile("prefetch.global.L2 [%0];" ::"l"(p));
}

__global__ void k_copy(const float4* __restrict__ src, float4* __restrict__ dst) {
  int i = blockIdx.x * 256 + threadIdx.x;
  dst[i] = src[i];
}

// L2 prefetch: only UNMASKED dta rows (+ deprel row load warms L2). grid 128, 256.
__global__ void __launch_bounds__(256) k_pref(const float* __restrict__ dta,
                                              const int* __restrict__ deprel,
                                              const int* __restrict__ asp_s,
                                              const int* __restrict__ asp_e) {
  int slot = blockIdx.x;
  int b = slot >> 3, il = slot & 7;
  int i = asp_s[b] + il;
  if (i > asp_e[b] || i >= Sdim) return;
  int tid = threadIdx.x;
  int dv = deprel[(size_t)(b * Sdim + i) * Sdim + tid];
  if (dv > 0) {
    const char* row = (const char*)(dta + (size_t)((b * Sdim + i) * Sdim + tid) * Ddim);
    prefetchL2(row);
    prefetchL2(row + 128);
  }
}

// u1/u2/c. grid 769, block 256.
__global__ void k_pre(const float* __restrict__ Wz, const float* __restrict__ bz,
                      const float* __restrict__ watt) {
  __shared__ float sm[8];
  int h = blockIdx.x, tid = threadIdx.x;
  float a1 = 0.f, a2 = 0.f;
  if (h < Hdim) {
    const float* wr = Wz + (size_t)h * Hdim;
    for (int k = tid; k < Hdim; k += 256) {
      float wv = wr[k];
      a1 = fmaf(wv, watt[k], a1);
      a2 = fmaf(wv, watt[Hdim + k], a2);
    }
  } else {
    for (int k = tid; k < Hdim; k += 256) {
      float bv = bz[k];
      a1 = fmaf(bv, watt[k], a1);
      a2 = fmaf(bv, watt[Hdim + k], a2);
    }
  }
  float r1 = blockReduceSum(a1, sm);
  float r2 = blockReduceSum(a2, sm);
  if (tid == 0) {
    if (h < Hdim) {
      g_u1[h] = r1;
      g_u2[h] = r2;
    } else {
      g_c[0] = r1;
      g_c[1] = r2;
    }
  }
}

// Attention with sparse compaction: ballot-compact unmasked j, stage only those
// dta rows, compute t2 on-the-fly for their (j+1) rows, logits/softmax/agg_d.
// grid (16,8), block 1024.
__global__ void __launch_bounds__(1024) k_att(
    const float* __restrict__ bert, const float* __restrict__ dta,
    const int* __restrict__ deprel, const int* __restrict__ asp_s,
    const int* __restrict__ asp_e, const float* __restrict__ w_att,
    const float* __restrict__ b_att) {
  extern __shared__ float dyns[];
  float* sD = dyns;                        // 68*256
  float* sm_s = dyns + 68 * 256;           // 256
  float* sm_p = sm_s + 256;                // 256
  float* sm_red = sm_p + 256;              // 32
  float* sm_agg = sm_red + 32;             // 1024
  int* sj = (int*)(sm_agg + 1024);         // 256
  float* st2 = (float*)(sj + 256);         // 256
  float* spc = st2 + 256;                  // 256
  int* swcnt = (int*)(spc + 256);          // 8
  int* sbase = swcnt + 8;                  // 9

  int b = blockIdx.x, il = blockIdx.y;
  int slot = b * 8 + il;
  int tid = threadIdx.x;

  int start = asp_s[b], endi = asp_e[b];
  int i = start + il;
  bool active = (i <= endi) && (i < Sdim);
  const int* deprow = deprel + (size_t)(b * Sdim + (active ? i : 0)) * Sdim;

  int flag = 0;
  if (active && tid < Sdim) flag = (deprow[tid] > 0) ? 1 : 0;
  int any = __syncthreads_or(flag);
  if (!active || !any) {
    if (tid < H4)
      ((float4*)g_X1)[(NSLOT + slot) * H4 + tid] = make_float4(0.f, 0.f, 0.f, 0.f);
    if (tid < Ddim) g_X2[slot * (Hdim + Ddim) + Hdim + tid] = 0.f;
    if (tid == 0) {
      g_cnt[slot] = 0;
      g_valid[slot] = 0;
      g_rowi[slot] = 0;
    }
    return;
  }

  // ballot-compact unmasked j (warps 0..7 cover j=0..255)
  unsigned bmask = 0;
  if (tid < Sdim) {
    bmask = __ballot_sync(0xffffffffu, flag);
    if ((tid & 31) == 0) swcnt[tid >> 5] = __popc(bmask);
  }
  __syncthreads();
  if (tid == 0) {
    int acc = 0;
#pragma unroll
    for (int w = 0; w < 8; ++w) {
      sbase[w] = acc;
      acc += swcnt[w];
    }
    sbase[8] = acc;
  }
  __syncthreads();
  int cnt = sbase[8];
  if (tid < Sdim && flag) {
    int pos = sbase[tid >> 5] + __popc(bmask & ((1u << (tid & 31)) - 1u));
    sj[pos] = tid;
  }
  if (tid < Sdim) sm_s[tid] = -1e9f;
  __syncthreads();

  // stage only compacted dta rows (16 float4 each)
  const float4* drow4 = (const float4*)(dta + (size_t)(b * Sdim + i) * Sdim * Ddim);
  for (int t = tid; t < cnt * 16; t += 1024) {
    int c = t >> 4, q = t & 15;
    cpasync16(saddr_of(sD + c * 68 + q * 4), drow4 + sj[c] * 16 + q);
  }
  cpasync_commit();

  int inext = (i + 1) & (Sdim - 1);
  const float* bi = bert + (size_t)(b * Sdim + inext) * Hdim;

  // s1 = bert[b,i+1] @ u1 (overlaps cp.async)
  float a = (tid < Hdim) ? bi[tid] * g_u1[tid] : 0.f;
  float s1 = blockReduceSum32(a, sm_red);
  float base = s1 + g_c[0] + b_att[0];

  // bert_next row -> X1[128+slot]
  if (tid < H4)
    ((float4*)g_X1)[(NSLOT + slot) * H4 + tid] = ((const float4*)bi)[tid];

  // t2 on the fly: warp per compacted j -> st2[c] = bert[b,(j+1)]@u2 + bz.w2
  {
    int w = tid >> 5, lane = tid & 31;
    const float4* u24 = (const float4*)g_u2;
    for (int c = w; c < cnt; c += 32) {
      int j1 = (sj[c] + 1) & (Sdim - 1);
      const float4* br = (const float4*)(bert + (size_t)(b * Sdim + j1) * Hdim);
      float a2 = 0.f;
#pragma unroll
      for (int k = lane; k < H4; k += 32) {
        float4 bv = br[k];
        float4 uv = u24[k];
        a2 = fmaf(bv.x, uv.x, a2);
        a2 = fmaf(bv.y, uv.y, a2);
        a2 = fmaf(bv.z, uv.z, a2);
        a2 = fmaf(bv.w, uv.w, a2);
      }
      a2 = warpReduceSum(a2);
      if (lane == 0) st2[c] = a2 + g_c[1];
    }
  }
  cpasync_wait0();
  __syncthreads();

  // logits for compacted j only: 4 threads per c
  {
    int c = tid >> 2, q = tid & 3;
    float acc = 0.f;
    if (c < cnt) {
      const float4* dj = (const float4*)(sD + c * 68) + q * 4;
      const float4* w34 = (const float4*)(w_att + 2 * Hdim) + q * 4;
#pragma unroll
      for (int k = 0; k < 4; ++k) {
        float4 d = dj[k];
        float4 w = w34[k];
        acc = fmaf(d.x, w.x, acc);
        acc = fmaf(d.y, w.y, acc);
        acc = fmaf(d.z, w.z, acc);
        acc = fmaf(d.w, w.w, acc);
      }
    }
    acc += __shfl_xor_sync(0xffffffffu, acc, 1);
    acc += __shfl_xor_sync(0xffffffffu, acc, 2);
    if (c < cnt && q == 0) {
      float s = base + st2[c] + acc;
      s = (s >= 0.f) ? s : 0.01f * s;
      sm_s[sj[c]] = s;
    }
  }
  __syncthreads();

  // softmax over full 256 (masked = -1e9 -> p = 0 exactly)
  float sv = (tid < Sdim) ? sm_s[tid] : -1e30f;
  float m = blockReduceMax32(sv, sm_red);
  float e = (tid < Sdim) ? expf(sv - m) : 0.f;
  float sum = blockReduceSum32(e, sm_red);
  if (tid < Sdim) sm_p[tid] = e / sum;
  __syncthreads();

  // compacted p list
  if (tid < cnt) {
    float p = sm_p[sj[tid]];
    spc[tid] = p;
    g_pl[slot * Sdim + tid] = p;
    g_jl[slot * Sdim + tid] = sj[tid];
  }
  __syncthreads();

  // agg_d over compacted rows: 16 parts x 64 d
  {
    int d = tid & 63, part = tid >> 6;
    float ad = 0.f;
    for (int c = part; c < cnt; c += 16) ad = fmaf(spc[c], sD[c * 68 + d], ad);
    sm_agg[tid] = ad;
    __syncthreads();
    if (tid < Ddim) {
      float t = 0.f;
#pragma unroll
      for (int p = 0; p < 16; ++p) t += sm_agg[p * 64 + tid];
      g_X2[slot * (Hdim + Ddim) + Hdim + tid] = t;
    }
  }
  if (tid == 0) {
    g_cnt[slot] = cnt;
    g_valid[slot] = 1;
    g_rowi[slot] = i;
  }
}

// v over compacted list: one block per slot, writes X1 row directly.
// grid 128, block 192.
__global__ void __launch_bounds__(192) k_v(const float* __restrict__ bert) {
  __shared__ float sp[Sdim];
  __shared__ int sjl[Sdim];
  int slot = blockIdx.x;
  int b = slot >> 3;
  int tid = threadIdx.x;
  int cnt = g_cnt[slot];
  for (int c = tid; c < cnt; c += 192) {
    sp[c] = g_pl[slot * Sdim + c];
    sjl[c] = (g_jl[slot * Sdim + c] + 1) & (Sdim - 1);
  }
  __syncthreads();
  const float4* bb4 = (const float4*)(bert + (size_t)b * Sdim * Hdim);
  float4 acc = make_float4(0.f, 0.f, 0.f, 0.f);
#pragma unroll 4
  for (int c = 0; c < cnt; ++c) {
    float p = sp[c];
    float4 bv = bb4[(size_t)sjl[c] * H4 + tid];
    acc.x = fmaf(p, bv.x, acc.x);
    acc.y = fmaf(p, bv.y, acc.y);
    acc.z = fmaf(p, bv.z, acc.z);
    acc.w = fmaf(p, bv.w, acc.w);
  }
  ((float4*)g_X1)[slot * H4 + tid] = acc;
}

#define FMAK4(C, WV, A0, A1, A2, A3)  \
  do {                                \
    unsigned long long s;             \
    s = splat2(x0.C);                 \
    ffma2(A0##l, s, (WV).x);          \
    ffma2(A0##h, s, (WV).y);          \
    s = splat2(x1.C);                 \
    ffma2(A1##l, s, (WV).x);          \
    ffma2(A1##h, s, (WV).y);          \
    s = splat2(x2.C);                 \
    ffma2(A2##l, s, (WV).x);          \
    ffma2(A2##h, s, (WV).y);          \
    s = splat2(x3.C);                 \
    ffma2(A3##l, s, (WV).x);          \
    ffma2(A3##h, s, (WV).y);          \
  } while (0)

// cp.async smem-staged K-split partial GEMM, 4 cols x 8 rows/thread, 64x128 tile.
template <int KS, int LDX, int NIT, int NROWS>
__global__ void __launch_bounds__(256) k_sgemm(const float* __restrict__ X,
                                               const float* __restrict__ W,
                                               float* __restrict__ P) {
  static_assert(KS == NIT * 32, "");
  __shared__ __align__(16) float sW[2][32 * 64];
  __shared__ __align__(16) float sX[2][128 * 32];

  int tid = threadIdx.x;
  int ct = tid & 15, rt = tid >> 4;
  int hb = blockIdx.x * 64;
  int rb = blockIdx.y * 128;
  int z = blockIdx.z;

  const float* Wg = W + (size_t)z * KS * Hdim + hb;
  const float* Xg = X + (size_t)rb * LDX + (size_t)z * KS;

  int wi = tid >> 4, wj = (tid & 15) * 4;
  int xi = tid >> 3, xj = (tid & 7) * 4;
  unsigned int sw0 = saddr_of(&sW[0][0]);
  unsigned int sx0 = saddr_of(&sX[0][0]);

#define LOAD_STAGE(stage, buf)                                                  \
  do {                                                                          \
    int k0 = (stage) * 32;                                                      \
    unsigned int swb = sw0 + (buf) * (32 * 64 * 4);                             \
    unsigned int sxb = sx0 + (buf) * (128 * 32 * 4);                            \
    cpasync16(swb + (wi * 64 + wj) * 4, Wg + (size_t)(k0 + wi) * Hdim + wj);    \
    cpasync16(swb + ((wi + 16) * 64 + wj) * 4,                                  \
              Wg + (size_t)(k0 + wi + 16) * Hdim + wj);                         \
    cpasync16(sxb + (xi * 32 + xj) * 4, Xg + (size_t)xi * LDX + k0 + xj);       \
    cpasync16(sxb + ((xi + 32) * 32 + xj) * 4,                                  \
              Xg + (size_t)(xi + 32) * LDX + k0 + xj);                          \
    cpasync16(sxb + ((xi + 64) * 32 + xj) * 4,                                  \
              Xg + (size_t)(xi + 64) * LDX + k0 + xj);                          \
    cpasync16(sxb + ((xi + 96) * 32 + xj) * 4,                                  \
              Xg + (size_t)(xi + 96) * LDX + k0 + xj);                          \
    cpasync_commit();                                                           \
  } while (0)

  LOAD_STAGE(0, 0);
  if (NIT > 1) LOAD_STAGE(1, 1);

  unsigned long long a0l = 0, a0h = 0, a1l = 0, a1h = 0;
  unsigned long long a2l = 0, a2h = 0, a3l = 0, a3h = 0;
  unsigned long long a4l = 0, a4h = 0, a5l = 0, a5h = 0;
  unsigned long long a6l = 0, a6h = 0, a7l = 0, a7h = 0;
  int r0 = rt * 8;

#pragma unroll 1
  for (int it = 0; it < NIT; ++it) {
    if (it < NIT - 1)
      cpasync_wait1();
    else
      cpasync_wait0();
    __syncthreads();
    int buf = it & 1;
    const float* xbase = &sX[buf][0];
    const float* wb = &sW[buf][ct * 4];
#pragma unroll
    for (int k4 = 0; k4 < 8; ++k4) {
      ulonglong2 w0 = *(const ulonglong2*)(wb + (k4 * 4 + 0) * 64);
      ulonglong2 w1 = *(const ulonglong2*)(wb + (k4 * 4 + 1) * 64);
      ulonglong2 w2 = *(const ulonglong2*)(wb + (k4 * 4 + 2) * 64);
      ulonglong2 w3 = *(const ulonglong2*)(wb + (k4 * 4 + 3) * 64);
      {
        float4 x0 = *(const float4*)(xbase + (r0 + 0) * 32 + k4 * 4);
        float4 x1 = *(const float4*)(xbase + (r0 + 1) * 32 + k4 * 4);
        float4 x2 = *(const float4*)(xbase + (r0 + 2) * 32 + k4 * 4);
        float4 x3 = *(const float4*)(xbase + (r0 + 3) * 32 + k4 * 4);
        FMAK4(x, w0, a0, a1, a2, a3);
        FMAK4(y, w1, a0, a1, a2, a3);
        FMAK4(z, w2, a0, a1, a2, a3);
        FMAK4(w, w3, a0, a1, a2, a3);
      }
      {
        float4 x0 = *(const float4*)(xbase + (r0 + 4) * 32 + k4 * 4);
        float4 x1 = *(const float4*)(xbase + (r0 + 5) * 32 + k4 * 4);
        float4 x2 = *(const float4*)(xbase + (r0 + 6) * 32 + k4 * 4);
        float4 x3 = *(const float4*)(xbase + (r0 + 7) * 32 + k4 * 4);
        FMAK4(x, w0, a4, a5, a6, a7);
        FMAK4(y, w1, a4, a5, a6, a7);
        FMAK4(z, w2, a4, a5, a6, a7);
        FMAK4(w, w3, a4, a5, a6, a7);
      }
    }
    __syncthreads();
    if (it + 2 < NIT) LOAD_STAGE(it + 2, buf);
  }
#undef LOAD_STAGE

  int r = rb + r0;
  float* pr = P + ((size_t)(z * NROWS + r)) * Hdim + hb + ct * 4;
#define STORE_ROW(q, A)                                                  \
  {                                                                      \
    float2 fl = u2f(A##l), fh = u2f(A##h);                               \
    *(float4*)(pr + (q)*Hdim) = make_float4(fl.x, fl.y, fh.x, fh.y);     \
  }
  STORE_ROW(0, a0)
  STORE_ROW(1, a1)
  STORE_ROW(2, a2)
  STORE_ROW(3, a3)
  STORE_ROW(4, a4)
  STORE_ROW(5, a5)
  STORE_ROW(6, a6)
  STORE_ROW(7, a7)
#undef STORE_ROW
}

// Epilogue: combine NZ K-split partials at OFF and route per MODE. block 192.
template <int NZ, int OFF, int NROWS, int MODE>
__global__ void __launch_bounds__(192) k_epi(const float* __restrict__ bias,
                                             float* __restrict__ outp) {
  int r = blockIdx.x;
  if (MODE == 2 && !g_valid[r]) return;
  int h = threadIdx.x * 4;
  float4 v = make_float4(0.f, 0.f, 0.f, 0.f);
#pragma unroll
  for (int zz = 0; zz < NZ; ++zz) {
    const float4 p =
        *(const float4*)(g_P + (size_t)(OFF + zz * NROWS + r) * Hdim + h);
    v.x += p.x;
    v.y += p.y;
    v.z += p.z;
    v.w += p.w;
  }
  if (MODE == 0) {
    const float4 bb = *(const float4*)(bias + h);
    v.x += bb.x;
    v.y += bb.y;
    v.z += bb.z;
    v.w += bb.w;
    if (r < NSLOT)
      *(float4*)(g_X2 + (size_t)r * (Hdim + Ddim) + h) = v;
    else
      *(float4*)(g_X3 + (size_t)(r - NSLOT) * (2 * Hdim) + Hdim + h) = v;
  } else if (MODE == 1) {
    *(float4*)(g_X3 + (size_t)r * (2 * Hdim) + h) = v;
  } else {
    int bb = r >> 3;
    int o = (g_rowi[r] + 1) & (Sdim - 1);
    *(float4*)(outp + ((size_t)(bb * Sdim + o)) * Hdim + h) = v;
  }
}

extern "C" void kernel_launch(void* const* d_in, const int* in_sizes, int n_in,
                              void* d_out, int out_size) {
  const float* bert = (const float*)d_in[0];
  const float* dta = (const float*)d_in[1];
  const int* deprel = (const int*)d_in[2];
  const int* asp_s = (const int*)d_in[3];
  const int* asp_e = (const int*)d_in[4];
  const float* Wz = (const float*)d_in[5];
  const float* bz = (const float*)d_in[6];
  const float* watt = (const float*)d_in[7];
  const float* batt = (const float*)d_in[8];
  const float* Wf = (const float*)d_in[9];
  const float* Wh = (const float*)d_in[10];
  float* out = (float*)d_out;

  float* P;
  float* X1;
  float* X2;
  float* X3;
  cudaGetSymbolAddress((void**)&P, g_P);
  cudaGetSymbolAddress((void**)&X1, g_X1);
  cudaGetSymbolAddress((void**)&X2, g_X2);
  cudaGetSymbolAddress((void**)&X3, g_X3);

  // Fork: bulk copy on s3; sparse L2 prefetch on s2.
  cudaEventRecord(g_evFork, 0);
  cudaStreamWaitEvent(g_s3, g_evFork, 0);
  cudaStreamWaitEvent(g_s2, g_evFork, 0);
  k_copy<<<(Bdim * Sdim * Hdim / 4) / 256, 256, 0, g_s3>>>((const float4*)bert,
                                                           (float4*)out);
  cudaEventRecord(g_evCopy, g_s3);
  k_pref<<<NSLOT, 256, 0, g_s2>>>(dta, deprel, asp_s, asp_e);
  cudaEventRecord(g_evPref, g_s2);

  // Critical path.
  k_pre<<<769, 256>>>(Wz, bz, watt);
  k_att<<<dim3(Bdim, 8), 1024, ATT_SMEM_FLOATS * 4>>>(bert, dta, deprel, asp_s,
                                                      asp_e, watt, batt);
  k_v<<<NSLOT, 192>>>(bert);
  // gemm0: X1(256 x 768) @ Wz   K=768 z=12 -> P0, epi adds bz
  k_sgemm<64, Hdim, 2, 256><<<dim3(12, 2, 12), 256>>>(X1, Wz, P + (size_t)P0_OFF * Hdim);
  k_epi<12, P0_OFF, 256, 0><<<256, 192>>>(bz, nullptr);
  // gemm1: X2(128 x 832) @ Wf   K=832 z=13 -> P1 -> nrep
  k_sgemm<64, Hdim + Ddim, 2, 128><<<dim3(12, 1, 13), 256>>>(X2, Wf,
                                                             P + (size_t)P1_OFF * Hdim);
  k_epi<13, P1_OFF, 128, 1><<<128, 192>>>(nullptr, nullptr);
  // gemm2: X3(128 x 1536) @ Wh  K=1536 z=24 -> P2 -> out scatter
  k_sgemm<64, 2 * Hdim, 2, 128><<<dim3(12, 1, 24), 256>>>(X3, Wh,
                                                          P + (size_t)P2_OFF * Hdim);
  // Join copy + prefetch streams, then scatter.
  cudaStreamWaitEvent(0, g_evCopy, 0);
  cudaStreamWaitEvent(0, g_evPref, 0);
  k_epi<24, P2_OFF, 128, 2><<<128, 192>>>(nullptr, out);
}

// round 16
// speedup vs baseline: 1.3210x; 1.0897x over previous
#include <cuda_runtime.h>
#include <cstdint>

#define Bdim 16
#define Sdim 256
#define Hdim 768
#define Ddim 64
#define NSLOT 128
#define H4 (Hdim / 4)

// Partial-sum row offsets inside g_P (rows of 768 floats)
#define P0_OFF 0      // gemm0 partials (12 x 256)
#define P1_OFF 3072   // gemm1 partials (13 x 128)
#define P2_OFF 4736   // gemm2 partials (24 x 128)
#define P_ROWS 7808

// Scratch (device globals; no allocation allowed)
__device__ __align__(16) float g_u1[Hdim];
__device__ __align__(16) float g_u2[Hdim];
__device__ float g_c[2];
__device__ __align__(16) float g_X1[2 * NSLOT * Hdim];  // 0-127: v; 128-255: bert_next
__device__ __align__(16) float g_X2[NSLOT * (Hdim + Ddim)];  // [agg_z | agg_d]
__device__ __align__(16) float g_X3[NSLOT * (2 * Hdim)];     // [nrep | zrow]
__device__ __align__(16) float g_P[(size_t)P_ROWS * Hdim];
__device__ int g_valid[NSLOT];
__device__ int g_rowi[NSLOT];

// k_att dynamic smem (floats): sD(68*256) s(256) p(256) red(32) agg(1024)
// sj(256) st2(256) spc(256) wcnt/base(17 -> pad 32)
#define ATT_SMEM_FLOATS (68 * 256 + 256 + 256 + 32 + 1024 + 256 + 256 + 256 + 32)

__global__ void __launch_bounds__(1024) k_att(const float*, const float*,
                                              const int*, const int*, const int*,
                                              const float*, const float*);

static cudaStream_t g_s2, g_s3;
static cudaEvent_t g_evFork, g_evCopy, g_evPref;
namespace {
struct HostInit {
  HostInit() {
    cudaStreamCreateWithFlags(&g_s2, cudaStreamNonBlocking);
    cudaStreamCreateWithFlags(&g_s3, cudaStreamNonBlocking);
    cudaEventCreateWithFlags(&g_evFork, cudaEventDisableTiming);
    cudaEventCreateWithFlags(&g_evCopy, cudaEventDisableTiming);
    cudaEventCreateWithFlags(&g_evPref, cudaEventDisableTiming);
    cudaFuncSetAttribute(k_att, cudaFuncAttributeMaxDynamicSharedMemorySize,
                         ATT_SMEM_FLOATS * 4);
  }
};
HostInit g_hostInit;
}  // namespace

__device__ __forceinline__ float warpReduceSum(float v) {
#pragma unroll
  for (int o = 16; o > 0; o >>= 1) v += __shfl_down_sync(0xffffffffu, v, o);
  return v;
}
__device__ __forceinline__ float warpReduceMax(float v) {
#pragma unroll
  for (int o = 16; o > 0; o >>= 1) v = fmaxf(v, __shfl_down_sync(0xffffffffu, v, o));
  return v;
}
__device__ __forceinline__ float blockReduceSum(float v, float* sm) {
  v = warpReduceSum(v);
  int w = threadIdx.x >> 5;
  if ((threadIdx.x & 31) == 0) sm[w] = v;
  __syncthreads();
  if (threadIdx.x < 8) {
    float x = sm[threadIdx.x];
#pragma unroll
    for (int o = 4; o > 0; o >>= 1) x += __shfl_down_sync(0xffu, x, o);
    if (threadIdx.x == 0) sm[0] = x;
  }
  __syncthreads();
  float r = sm[0];
  __syncthreads();
  return r;
}
__device__ __forceinline__ float blockReduceSum32(float v, float* sm) {
  v = warpReduceSum(v);
  int w = threadIdx.x >> 5;
  if ((threadIdx.x & 31) == 0) sm[w] = v;
  __syncthreads();
  if (threadIdx.x < 32) {
    float x = warpReduceSum(sm[threadIdx.x]);
    if (threadIdx.x == 0) sm[0] = x;
  }
  __syncthreads();
  float r = sm[0];
  __syncthreads();
  return r;
}
__device__ __forceinline__ float blockReduceMax32(float v, float* sm) {
  v = warpReduceMax(v);
  int w = threadIdx.x >> 5;
  if ((threadIdx.x & 31) == 0) sm[w] = v;
  __syncthreads();
  if (threadIdx.x < 32) {
    float x = warpReduceMax(sm[threadIdx.x]);
    if (threadIdx.x == 0) sm[0] = x;
  }
  __syncthreads();
  float r = sm[0];
  __syncthreads();
  return r;
}

// ---- packed f32x2 helpers ----
__device__ __forceinline__ unsigned long long splat2(float x) {
  unsigned long long r;
  asm("mov.b64 %0, {%1, %2};" : "=l"(r) : "f"(x), "f"(x));
  return r;
}
__device__ __forceinline__ void ffma2(unsigned long long& a, unsigned long long x,
                                      unsigned long long w) {
  asm("fma.rn.f32x2 %0, %1, %2, %0;" : "+l"(a) : "l"(x), "l"(w));
}
__device__ __forceinline__ float2 u2f(unsigned long long v) {
  float2 f;
  asm("mov.b64 {%0, %1}, %2;" : "=f"(f.x), "=f"(f.y) : "l"(v));
  return f;
}

// ---- cp.async helpers ----
__device__ __forceinline__ unsigned int saddr_of(const void* p) {
  return (unsigned int)__cvta_generic_to_shared(p);
}
__device__ __forceinline__ void cpasync16(unsigned int saddr, const void* g) {
  asm volatile("cp.async.ca.shared.global [%0], [%1], 16;" ::"r"(saddr), "l"(g));
}
__device__ __forceinline__ void cpasync_commit() {
  asm volatile("cp.async.commit_group;" ::: "memory");
}
__device__ __forceinline__ void cpasync_wait1() {
  asm volatile("cp.async.wait_group 1;" ::: "memory");
}
__device__ __forceinline__ void cpasync_wait0() {
  asm volatile("cp.async.wait_group 0;" ::: "memory");
}
__device__ __forceinline__ void prefetchL2(const void* p) {
  asm volatile("prefetch.global.L2 [%0];" ::"l"(p));
}

__global__ void k_copy(const float4* __restrict__ src, float4* __restrict__ dst) {
  int i = blockIdx.x * 256 + threadIdx.x;
  dst[i] = src[i];
}

// L2 prefetch: only UNMASKED dta rows. grid 128, block 256.
__global__ void __launch_bounds__(256) k_pref(const float* __restrict__ dta,
                                              const int* __restrict__ deprel,
                                              const int* __restrict__ asp_s,
                                              const int* __restrict__ asp_e) {
  int slot = blockIdx.x;
  int b = slot >> 3, il = slot & 7;
  int i = asp_s[b] + il;
  if (i > asp_e[b] || i >= Sdim) return;
  int tid = threadIdx.x;
  int dv = deprel[(size_t)(b * Sdim + i) * Sdim + tid];
  if (dv > 0) {
    const char* row = (const char*)(dta + (size_t)((b * Sdim + i) * Sdim + tid) * Ddim);
    prefetchL2(row);
    prefetchL2(row + 128);
  }
}

// u1/u2/c. grid 769, block 256.
__global__ void k_pre(const float* __restrict__ Wz, const float* __restrict__ bz,
                      const float* __restrict__ watt) {
  __shared__ float sm[8];
  int h = blockIdx.x, tid = threadIdx.x;
  float a1 = 0.f, a2 = 0.f;
  if (h < Hdim) {
    const float* wr = Wz + (size_t)h * Hdim;
    for (int k = tid; k < Hdim; k += 256) {
      float wv = wr[k];
      a1 = fmaf(wv, watt[k], a1);
      a2 = fmaf(wv, watt[Hdim + k], a2);
    }
  } else {
    for (int k = tid; k < Hdim; k += 256) {
      float bv = bz[k];
      a1 = fmaf(bv, watt[k], a1);
      a2 = fmaf(bv, watt[Hdim + k], a2);
    }
  }
  float r1 = blockReduceSum(a1, sm);
  float r2 = blockReduceSum(a2, sm);
  if (tid == 0) {
    if (h < Hdim) {
      g_u1[h] = r1;
      g_u2[h] = r2;
    } else {
      g_c[0] = r1;
      g_c[1] = r2;
    }
  }
}

// Attention with sparse compaction + fused v. Warps 0-23 compute t2 dots while
// warps 24-31 compute s1; after softmax, threads 0-191 accumulate v from the
// (L1-hot) bert rows the t2 phase just read. grid (16,8), block 1024.
__global__ void __launch_bounds__(1024) k_att(
    const float* __restrict__ bert, const float* __restrict__ dta,
    const int* __restrict__ deprel, const int* __restrict__ asp_s,
    const int* __restrict__ asp_e, const float* __restrict__ w_att,
    const float* __restrict__ b_att) {
  extern __shared__ float dyns[];
  float* sD = dyns;                        // 68*256
  float* sm_s = dyns + 68 * 256;           // 256
  float* sm_p = sm_s + 256;                // 256
  float* sm_red = sm_p + 256;              // 32
  float* sm_agg = sm_red + 32;             // 1024
  int* sj = (int*)(sm_agg + 1024);         // 256
  float* st2 = (float*)(sj + 256);         // 256
  float* spc = st2 + 256;                  // 256
  int* swcnt = (int*)(spc + 256);          // 8
  int* sbase = swcnt + 8;                  // 9
  float* ss1 = (float*)(sbase + 9);        // 8 (s1 warp partials)

  int b = blockIdx.x, il = blockIdx.y;
  int slot = b * 8 + il;
  int tid = threadIdx.x;
  int w = tid >> 5, lane = tid & 31;

  int start = asp_s[b], endi = asp_e[b];
  int i = start + il;
  bool active = (i <= endi) && (i < Sdim);
  const int* deprow = deprel + (size_t)(b * Sdim + (active ? i : 0)) * Sdim;

  int flag = 0;
  if (active && tid < Sdim) flag = (deprow[tid] > 0) ? 1 : 0;
  int any = __syncthreads_or(flag);
  if (!active || !any) {
    if (tid < H4) {
      float4 z = make_float4(0.f, 0.f, 0.f, 0.f);
      ((float4*)g_X1)[slot * H4 + tid] = z;
      ((float4*)g_X1)[(NSLOT + slot) * H4 + tid] = z;
    }
    if (tid < Ddim) g_X2[slot * (Hdim + Ddim) + Hdim + tid] = 0.f;
    if (tid == 0) {
      g_valid[slot] = 0;
      g_rowi[slot] = 0;
    }
    return;
  }

  // ballot-compact unmasked j (warps 0..7 cover j=0..255)
  unsigned bmask = 0;
  if (tid < Sdim) {
    bmask = __ballot_sync(0xffffffffu, flag);
    if ((tid & 31) == 0) swcnt[tid >> 5] = __popc(bmask);
  }
  __syncthreads();
  if (tid == 0) {
    int acc = 0;
#pragma unroll
    for (int ww = 0; ww < 8; ++ww) {
      sbase[ww] = acc;
      acc += swcnt[ww];
    }
    sbase[8] = acc;
  }
  __syncthreads();
  int cnt = sbase[8];
  if (tid < Sdim && flag) {
    int pos = sbase[tid >> 5] + __popc(bmask & ((1u << (tid & 31)) - 1u));
    sj[pos] = tid;
  }
  if (tid < Sdim) sm_s[tid] = -1e9f;
  __syncthreads();

  // stage only compacted dta rows (16 float4 each)
  const float4* drow4 = (const float4*)(dta + (size_t)(b * Sdim + i) * Sdim * Ddim);
  for (int t = tid; t < cnt * 16; t += 1024) {
    int c = t >> 4, q = t & 15;
    cpasync16(saddr_of(sD + c * 68 + q * 4), drow4 + sj[c] * 16 + q);
  }
  cpasync_commit();

  int inext = (i + 1) & (Sdim - 1);
  const float* bi = bert + (size_t)(b * Sdim + inext) * Hdim;

  // bert_next row -> X1[128+slot]
  if (tid < H4)
    ((float4*)g_X1)[(NSLOT + slot) * H4 + tid] = ((const float4*)bi)[tid];

  // PARALLEL: warps 0-23 -> t2 dots for compacted rows; warps 24-31 -> s1.
  if (w < 24) {
    const float4* u24 = (const float4*)g_u2;
    for (int c = w; c < cnt; c += 24) {
      int j1 = (sj[c] + 1) & (Sdim - 1);
      const float4* br = (const float4*)(bert + (size_t)(b * Sdim + j1) * Hdim);
      float a2 = 0.f;
#pragma unroll
      for (int k = lane; k < H4; k += 32) {
        float4 bv = br[k];
        float4 uv = u24[k];
        a2 = fmaf(bv.x, uv.x, a2);
        a2 = fmaf(bv.y, uv.y, a2);
        a2 = fmaf(bv.z, uv.z, a2);
        a2 = fmaf(bv.w, uv.w, a2);
      }
      a2 = warpReduceSum(a2);
      if (lane == 0) st2[c] = a2 + g_c[1];
    }
  } else {
    int t = tid - 768;  // 0..255
    float a = bi[t] * g_u1[t] + bi[t + 256] * g_u1[t + 256] +
              bi[t + 512] * g_u1[t + 512];
    a = warpReduceSum(a);
    if (lane == 0) ss1[w - 24] = a;
  }
  cpasync_wait0();
  __syncthreads();

  float s1 = ss1[0] + ss1[1] + ss1[2] + ss1[3] + ss1[4] + ss1[5] + ss1[6] + ss1[7];
  float base = s1 + g_c[0] + b_att[0];

  // logits for compacted j only: 4 threads per c
  {
    int c = tid >> 2, q = tid & 3;
    float acc = 0.f;
    if (c < cnt) {
      const float4* dj = (const float4*)(sD + c * 68) + q * 4;
      const float4* w34 = (const float4*)(w_att + 2 * Hdim) + q * 4;
#pragma unroll
      for (int k = 0; k < 4; ++k) {
        float4 d = dj[k];
        float4 ww = w34[k];
        acc = fmaf(d.x, ww.x, acc);
        acc = fmaf(d.y, ww.y, acc);
        acc = fmaf(d.z, ww.z, acc);
        acc = fmaf(d.w, ww.w, acc);
      }
    }
    acc += __shfl_xor_sync(0xffffffffu, acc, 1);
    acc += __shfl_xor_sync(0xffffffffu, acc, 2);
    if (c < cnt && q == 0) {
      float s = base + st2[c] + acc;
      s = (s >= 0.f) ? s : 0.01f * s;
      sm_s[sj[c]] = s;
    }
  }
  __syncthreads();

  // softmax over full 256 (masked = -1e9 -> p = 0 exactly)
  float sv = (tid < Sdim) ? sm_s[tid] : -1e30f;
  float m = blockReduceMax32(sv, sm_red);
  float e = (tid < Sdim) ? expf(sv - m) : 0.f;
  float sum = blockReduceSum32(e, sm_red);
  if (tid < Sdim) sm_p[tid] = e / sum;
  __syncthreads();

  if (tid < cnt) spc[tid] = sm_p[sj[tid]];
  __syncthreads();

  // agg_d over compacted rows: 16 parts x 64 d. Concurrently, threads 0-191
  // of the SAME phase can't run v (needs spc), so v comes after one sync.
  {
    int d = tid & 63, part = tid >> 6;
    float ad = 0.f;
    for (int c = part; c < cnt; c += 16) ad = fmaf(spc[c], sD[c * 68 + d], ad);
    sm_agg[tid] = ad;
  }
  __syncthreads();
  if (tid < Ddim) {
    float t = 0.f;
#pragma unroll
    for (int p = 0; p < 16; ++p) t += sm_agg[p * 64 + tid];
    g_X2[slot * (Hdim + Ddim) + Hdim + tid] = t;
  }

  // fused v: threads 0-191, compacted bert rows are L1-hot from the t2 phase.
  if (tid < H4) {
    const float4* bb4 = (const float4*)(bert + (size_t)b * Sdim * Hdim);
    float4 acc = make_float4(0.f, 0.f, 0.f, 0.f);
    for (int c = 0; c < cnt; ++c) {
      float p = spc[c];
      int j1 = (sj[c] + 1) & (Sdim - 1);
      float4 bv = bb4[(size_t)j1 * H4 + tid];
      acc.x = fmaf(p, bv.x, acc.x);
      acc.y = fmaf(p, bv.y, acc.y);
      acc.z = fmaf(p, bv.z, acc.z);
      acc.w = fmaf(p, bv.w, acc.w);
    }
    ((float4*)g_X1)[slot * H4 + tid] = acc;
  }
  if (tid == 0) {
    g_valid[slot] = 1;
    g_rowi[slot] = i;
  }
}

#define FMAK4(C, WV, A0, A1, A2, A3)  \
  do {                                \
    unsigned long long s;             \
    s = splat2(x0.C);                 \
    ffma2(A0##l, s, (WV).x);          \
    ffma2(A0##h, s, (WV).y);          \
    s = splat2(x1.C);                 \
    ffma2(A1##l, s, (WV).x);          \
    ffma2(A1##h, s, (WV).y);          \
    s = splat2(x2.C);                 \
    ffma2(A2##l, s, (WV).x);          \
    ffma2(A2##h, s, (WV).y);          \
    s = splat2(x3.C);                 \
    ffma2(A3##l, s, (WV).x);          \
    ffma2(A3##h, s, (WV).y);          \
  } while (0)

// cp.async smem-staged K-split partial GEMM, 4 cols x 8 rows/thread, 64x128 tile.
template <int KS, int LDX, int NIT, int NROWS>
__global__ void __launch_bounds__(256) k_sgemm(const float* __restrict__ X,
                                               const float* __restrict__ W,
                                               float* __restrict__ P) {
  static_assert(KS == NIT * 32, "");
  __shared__ __align__(16) float sW[2][32 * 64];
  __shared__ __align__(16) float sX[2][128 * 32];

  int tid = threadIdx.x;
  int ct = tid & 15, rt = tid >> 4;
  int hb = blockIdx.x * 64;
  int rb = blockIdx.y * 128;
  int z = blockIdx.z;

  const float* Wg = W + (size_t)z * KS * Hdim + hb;
  const float* Xg = X + (size_t)rb * LDX + (size_t)z * KS;

  int wi = tid >> 4, wj = (tid & 15) * 4;
  int xi = tid >> 3, xj = (tid & 7) * 4;
  unsigned int sw0 = saddr_of(&sW[0][0]);
  unsigned int sx0 = saddr_of(&sX[0][0]);

#define LOAD_STAGE(stage, buf)                                                  \
  do {                                                                          \
    int k0 = (stage) * 32;                                                      \
    unsigned int swb = sw0 + (buf) * (32 * 64 * 4);                             \
    unsigned int sxb = sx0 + (buf) * (128 * 32 * 4);                            \
    cpasync16(swb + (wi * 64 + wj) * 4, Wg + (size_t)(k0 + wi) * Hdim + wj);    \
    cpasync16(swb + ((wi + 16) * 64 + wj) * 4,                                  \
              Wg + (size_t)(k0 + wi + 16) * Hdim + wj);                         \
    cpasync16(sxb + (xi * 32 + xj) * 4, Xg + (size_t)xi * LDX + k0 + xj);       \
    cpasync16(sxb + ((xi + 32) * 32 + xj) * 4,                                  \
              Xg + (size_t)(xi + 32) * LDX + k0 + xj);                          \
    cpasync16(sxb + ((xi + 64) * 32 + xj) * 4,                                  \
              Xg + (size_t)(xi + 64) * LDX + k0 + xj);                          \
    cpasync16(sxb + ((xi + 96) * 32 + xj) * 4,                                  \
              Xg + (size_t)(xi + 96) * LDX + k0 + xj);                          \
    cpasync_commit();                                                           \
  } while (0)

  LOAD_STAGE(0, 0);
  if (NIT > 1) LOAD_STAGE(1, 1);

  unsigned long long a0l = 0, a0h = 0, a1l = 0, a1h = 0;
  unsigned long long a2l = 0, a2h = 0, a3l = 0, a3h = 0;
  unsigned long long a4l = 0, a4h = 0, a5l = 0, a5h = 0;
  unsigned long long a6l = 0, a6h = 0, a7l = 0, a7h = 0;
  int r0 = rt * 8;

#pragma unroll 1
  for (int it = 0; it < NIT; ++it) {
    if (it < NIT - 1)
      cpasync_wait1();
    else
      cpasync_wait0();
    __syncthreads();
    int buf = it & 1;
    const float* xbase = &sX[buf][0];
    const float* wb = &sW[buf][ct * 4];
#pragma unroll
    for (int k4 = 0; k4 < 8; ++k4) {
      ulonglong2 w0 = *(const ulonglong2*)(wb + (k4 * 4 + 0) * 64);
      ulonglong2 w1 = *(const ulonglong2*)(wb + (k4 * 4 + 1) * 64);
      ulonglong2 w2 = *(const ulonglong2*)(wb + (k4 * 4 + 2) * 64);
      ulonglong2 w3 = *(const ulonglong2*)(wb + (k4 * 4 + 3) * 64);
      {
        float4 x0 = *(const float4*)(xbase + (r0 + 0) * 32 + k4 * 4);
        float4 x1 = *(const float4*)(xbase + (r0 + 1) * 32 + k4 * 4);
        float4 x2 = *(const float4*)(xbase + (r0 + 2) * 32 + k4 * 4);
        float4 x3 = *(const float4*)(xbase + (r0 + 3) * 32 + k4 * 4);
        FMAK4(x, w0, a0, a1, a2, a3);
        FMAK4(y, w1, a0, a1, a2, a3);
        FMAK4(z, w2, a0, a1, a2, a3);
        FMAK4(w, w3, a0, a1, a2, a3);
      }
      {
        float4 x0 = *(const float4*)(xbase + (r0 + 4) * 32 + k4 * 4);
        float4 x1 = *(const float4*)(xbase + (r0 + 5) * 32 + k4 * 4);
        float4 x2 = *(const float4*)(xbase + (r0 + 6) * 32 + k4 * 4);
        float4 x3 = *(const float4*)(xbase + (r0 + 7) * 32 + k4 * 4);
        FMAK4(x, w0, a4, a5, a6, a7);
        FMAK4(y, w1, a4, a5, a6, a7);
        FMAK4(z, w2, a4, a5, a6, a7);
        FMAK4(w, w3, a4, a5, a6, a7);
      }
    }
    __syncthreads();
    if (it + 2 < NIT) LOAD_STAGE(it + 2, buf);
  }
#undef LOAD_STAGE

  int r = rb + r0;
  float* pr = P + ((size_t)(z * NROWS + r)) * Hdim + hb + ct * 4;
#define STORE_ROW(q, A)                                                  \
  {                                                                      \
    float2 fl = u2f(A##l), fh = u2f(A##h);                               \
    *(float4*)(pr + (q)*Hdim) = make_float4(fl.x, fl.y, fh.x, fh.y);     \
  }
  STORE_ROW(0, a0)
  STORE_ROW(1, a1)
  STORE_ROW(2, a2)
  STORE_ROW(3, a3)
  STORE_ROW(4, a4)
  STORE_ROW(5, a5)
  STORE_ROW(6, a6)
  STORE_ROW(7, a7)
#undef STORE_ROW
}

// Epilogue: combine NZ K-split partials at OFF and route per MODE. block 192.
template <int NZ, int OFF, int NROWS, int MODE>
__global__ void __launch_bounds__(192) k_epi(const float* __restrict__ bias,
                                             float* __restrict__ outp) {
  int r = blockIdx.x;
  if (MODE == 2 && !g_valid[r]) return;
  int h = threadIdx.x * 4;
  float4 v = make_float4(0.f, 0.f, 0.f, 0.f);
#pragma unroll
  for (int zz = 0; zz < NZ; ++zz) {
    const float4 p =
        *(const float4*)(g_P + (size_t)(OFF + zz * NROWS + r) * Hdim + h);
    v.x += p.x;
    v.y += p.y;
    v.z += p.z;
    v.w += p.w;
  }
  if (MODE == 0) {
    const float4 bb = *(const float4*)(bias + h);
    v.x += bb.x;
    v.y += bb.y;
    v.z += bb.z;
    v.w += bb.w;
    if (r < NSLOT)
      *(float4*)(g_X2 + (size_t)r * (Hdim + Ddim) + h) = v;
    else
      *(float4*)(g_X3 + (size_t)(r - NSLOT) * (2 * Hdim) + Hdim + h) = v;
  } else if (MODE == 1) {
    *(float4*)(g_X3 + (size_t)r * (2 * Hdim) + h) = v;
  } else {
    int bb = r >> 3;
    int o = (g_rowi[r] + 1) & (Sdim - 1);
    *(float4*)(outp + ((size_t)(bb * Sdim + o)) * Hdim + h) = v;
  }
}

extern "C" void kernel_launch(void* const* d_in, const int* in_sizes, int n_in,
                              void* d_out, int out_size) {
  const float* bert = (const float*)d_in[0];
  const float* dta = (const float*)d_in[1];
  const int* deprel = (const int*)d_in[2];
  const int* asp_s = (const int*)d_in[3];
  const int* asp_e = (const int*)d_in[4];
  const float* Wz = (const float*)d_in[5];
  const float* bz = (const float*)d_in[6];
  const float* watt = (const float*)d_in[7];
  const float* batt = (const float*)d_in[8];
  const float* Wf = (const float*)d_in[9];
  const float* Wh = (const float*)d_in[10];
  float* out = (float*)d_out;

  float* P;
  float* X1;
  float* X2;
  float* X3;
  cudaGetSymbolAddress((void**)&P, g_P);
  cudaGetSymbolAddress((void**)&X1, g_X1);
  cudaGetSymbolAddress((void**)&X2, g_X2);
  cudaGetSymbolAddress((void**)&X3, g_X3);

  // Fork: bulk copy on s3; sparse L2 prefetch on s2.
  cudaEventRecord(g_evFork, 0);
  cudaStreamWaitEvent(g_s3, g_evFork, 0);
  cudaStreamWaitEvent(g_s2, g_evFork, 0);
  k_copy<<<(Bdim * Sdim * Hdim / 4) / 256, 256, 0, g_s3>>>((const float4*)bert,
                                                           (float4*)out);
  cudaEventRecord(g_evCopy, g_s3);
  k_pref<<<NSLOT, 256, 0, g_s2>>>(dta, deprel, asp_s, asp_e);
  cudaEventRecord(g_evPref, g_s2);

  // Critical path.
  k_pre<<<769, 256>>>(Wz, bz, watt);
  k_att<<<dim3(Bdim, 8), 1024, ATT_SMEM_FLOATS * 4>>>(bert, dta, deprel, asp_s,
                                                      asp_e, watt, batt);
  // gemm0: X1(256 x 768) @ Wz   K=768 z=12 -> P0, epi adds bz
  k_sgemm<64, Hdim, 2, 256><<<dim3(12, 2, 12), 256>>>(X1, Wz, P + (size_t)P0_OFF * Hdim);
  k_epi<12, P0_OFF, 256, 0><<<256, 192>>>(bz, nullptr);
  // gemm1: X2(128 x 832) @ Wf   K=832 z=13 -> P1 -> nrep
  k_sgemm<64, Hdim + Ddim, 2, 128><<<dim3(12, 1, 13), 256>>>(X2, Wf,
                                                             P + (size_t)P1_OFF * Hdim);
  k_epi<13, P1_OFF, 128, 1><<<128, 192>>>(nullptr, nullptr);
  // gemm2: X3(128 x 1536) @ Wh  K=1536 z=24 -> P2 -> out scatter
  k_sgemm<64, 2 * Hdim, 2, 128><<<dim3(12, 1, 24), 256>>>(X3, Wh,
                                                          P + (size_t)P2_OFF * Hdim);
  // Join copy + prefetch streams, then scatter.
  cudaStreamWaitEvent(0, g_evCopy, 0);
  cudaStreamWaitEvent(0, g_evPref, 0);
  k_epi<24, P2_OFF, 128, 2><<<128, 192>>>(nullptr, out);
}

// round 17
// speedup vs baseline: 1.3774x; 1.0427x over previous
#include <cuda_runtime.h>
#include <cstdint>

#define Bdim 16
#define Sdim 256
#define Hdim 768
#define Ddim 64
#define NSLOT 128
#define H4 (Hdim / 4)

// Partial-sum row offsets inside g_P (rows of 768 floats)
#define P0_OFF 0      // gemm0 partials (12 x 256)
#define P1_OFF 3072   // gemm1 partials (13 x 128)
#define P2_OFF 4736   // gemm2 partials (24 x 128)
#define P_ROWS 7808

// Scratch (device globals; no allocation allowed)
__device__ __align__(16) float g_u1[Hdim];
__device__ __align__(16) float g_u2[Hdim];
__device__ float g_c[2];
__device__ __align__(16) float g_X1[2 * NSLOT * Hdim];  // 0-127: v; 128-255: bert_next
__device__ __align__(16) float g_X2[NSLOT * (Hdim + Ddim)];  // [agg_z | agg_d]
__device__ __align__(16) float g_X3[NSLOT * (2 * Hdim)];     // [nrep | zrow]
__device__ __align__(16) float g_P[(size_t)P_ROWS * Hdim];
__device__ int g_valid[NSLOT];
__device__ int g_rowi[NSLOT];

// k_att dynamic smem (floats): sD(68*256) sc(256) spc(256) red(32) agg(768)
// sj(256) st2(256) wcnt(8) base(9) ss1(8)
#define ATT_SMEM_FLOATS (68 * 256 + 256 + 256 + 32 + 768 + 256 + 256 + 32)

__global__ void __launch_bounds__(1024) k_att(const float*, const float*,
                                              const int*, const int*, const int*,
                                              const float*, const float*);

static cudaStream_t g_s2, g_s3;
static cudaEvent_t g_evFork, g_evCopy, g_evPref;
namespace {
struct HostInit {
  HostInit() {
    cudaStreamCreateWithFlags(&g_s2, cudaStreamNonBlocking);
    cudaStreamCreateWithFlags(&g_s3, cudaStreamNonBlocking);
    cudaEventCreateWithFlags(&g_evFork, cudaEventDisableTiming);
    cudaEventCreateWithFlags(&g_evCopy, cudaEventDisableTiming);
    cudaEventCreateWithFlags(&g_evPref, cudaEventDisableTiming);
    cudaFuncSetAttribute(k_att, cudaFuncAttributeMaxDynamicSharedMemorySize,
                         ATT_SMEM_FLOATS * 4);
  }
};
HostInit g_hostInit;
}  // namespace

__device__ __forceinline__ float warpReduceSum(float v) {
#pragma unroll
  for (int o = 16; o > 0; o >>= 1) v += __shfl_down_sync(0xffffffffu, v, o);
  return v;
}
__device__ __forceinline__ float warpReduceMax(float v) {
#pragma unroll
  for (int o = 16; o > 0; o >>= 1) v = fmaxf(v, __shfl_down_sync(0xffffffffu, v, o));
  return v;
}
__device__ __forceinline__ float blockReduceSum(float v, float* sm) {
  v = warpReduceSum(v);
  int w = threadIdx.x >> 5;
  if ((threadIdx.x & 31) == 0) sm[w] = v;
  __syncthreads();
  if (threadIdx.x < 8) {
    float x = sm[threadIdx.x];
#pragma unroll
    for (int o = 4; o > 0; o >>= 1) x += __shfl_down_sync(0xffu, x, o);
    if (threadIdx.x == 0) sm[0] = x;
  }
  __syncthreads();
  float r = sm[0];
  __syncthreads();
  return r;
}
__device__ __forceinline__ float blockReduceSum32(float v, float* sm) {
  v = warpReduceSum(v);
  int w = threadIdx.x >> 5;
  if ((threadIdx.x & 31) == 0) sm[w] = v;
  __syncthreads();
  if (threadIdx.x < 32) {
    float x = warpReduceSum(sm[threadIdx.x]);
    if (threadIdx.x == 0) sm[0] = x;
  }
  __syncthreads();
  float r = sm[0];
  __syncthreads();
  return r;
}
__device__ __forceinline__ float blockReduceMax32(float v, float* sm) {
  v = warpReduceMax(v);
  int w = threadIdx.x >> 5;
  if ((threadIdx.x & 31) == 0) sm[w] = v;
  __syncthreads();
  if (threadIdx.x < 32) {
    float x = warpReduceMax(sm[threadIdx.x]);
    if (threadIdx.x == 0) sm[0] = x;
  }
  __syncthreads();
  float r = sm[0];
  __syncthreads();
  return r;
}

// ---- packed f32x2 helpers ----
__device__ __forceinline__ unsigned long long splat2(float x) {
  unsigned long long r;
  asm("mov.b64 %0, {%1, %2};" : "=l"(r) : "f"(x), "f"(x));
  return r;
}
__device__ __forceinline__ void ffma2(unsigned long long& a, unsigned long long x,
                                      unsigned long long w) {
  asm("fma.rn.f32x2 %0, %1, %2, %0;" : "+l"(a) : "l"(x), "l"(w));
}
__device__ __forceinline__ float2 u2f(unsigned long long v) {
  float2 f;
  asm("mov.b64 {%0, %1}, %2;" : "=f"(f.x), "=f"(f.y) : "l"(v));
  return f;
}

// ---- cp.async helpers ----
__device__ __forceinline__ unsigned int saddr_of(const void* p) {
  return (unsigned int)__cvta_generic_to_shared(p);
}
__device__ __forceinline__ void cpasync16(unsigned int saddr, const void* g) {
  asm volatile("cp.async.ca.shared.global [%0], [%1], 16;" ::"r"(saddr), "l"(g));
}
__device__ __forceinline__ void cpasync_commit() {
  asm volatile("cp.async.commit_group;" ::: "memory");
}
__device__ __forceinline__ void cpasync_wait1() {
  asm volatile("cp.async.wait_group 1;" ::: "memory");
}
__device__ __forceinline__ void cpasync_wait0() {
  asm volatile("cp.async.wait_group 0;" ::: "memory");
}
__device__ __forceinline__ void prefetchL2(const void* p) {
  asm volatile("prefetch.global.L2 [%0];" ::"l"(p));
}

__global__ void k_copy(const float4* __restrict__ src, float4* __restrict__ dst) {
  int i = blockIdx.x * 256 + threadIdx.x;
  dst[i] = src[i];
}

// L2 prefetch: only UNMASKED dta rows. grid 128, block 256.
__global__ void __launch_bounds__(256) k_pref(const float* __restrict__ dta,
                                              const int* __restrict__ deprel,
                                              const int* __restrict__ asp_s,
                                              const int* __restrict__ asp_e) {
  int slot = blockIdx.x;
  int b = slot >> 3, il = slot & 7;
  int i = asp_s[b] + il;
  if (i > asp_e[b] || i >= Sdim) return;
  int tid = threadIdx.x;
  int dv = deprel[(size_t)(b * Sdim + i) * Sdim + tid];
  if (dv > 0) {
    const char* row = (const char*)(dta + (size_t)((b * Sdim + i) * Sdim + tid) * Ddim);
    prefetchL2(row);
    prefetchL2(row + 128);
  }
}

// u1/u2/c. grid 769, block 256.
__global__ void k_pre(const float* __restrict__ Wz, const float* __restrict__ bz,
                      const float* __restrict__ watt) {
  __shared__ float sm[8];
  int h = blockIdx.x, tid = threadIdx.x;
  float a1 = 0.f, a2 = 0.f;
  if (h < Hdim) {
    const float* wr = Wz + (size_t)h * Hdim;
    for (int k = tid; k < Hdim; k += 256) {
      float wv = wr[k];
      a1 = fmaf(wv, watt[k], a1);
      a2 = fmaf(wv, watt[Hdim + k], a2);
    }
  } else {
    for (int k = tid; k < Hdim; k += 256) {
      float bv = bz[k];
      a1 = fmaf(bv, watt[k], a1);
      a2 = fmaf(bv, watt[Hdim + k], a2);
    }
  }
  float r1 = blockReduceSum(a1, sm);
  float r2 = blockReduceSum(a2, sm);
  if (tid == 0) {
    if (h < Hdim) {
      g_u1[h] = r1;
      g_u2[h] = r2;
    } else {
      g_c[0] = r1;
      g_c[1] = r2;
    }
  }
}

// Attention, sparse-compacted, softmax over compacted list only (masked j have
// p==0 exactly). Warps 0-23: t2 dots; 24-31: s1. v (thr 0-191) runs in
// parallel with agg_d (thr 256-1023). grid (16,8), block 1024.
__global__ void __launch_bounds__(1024) k_att(
    const float* __restrict__ bert, const float* __restrict__ dta,
    const int* __restrict__ deprel, const int* __restrict__ asp_s,
    const int* __restrict__ asp_e, const float* __restrict__ w_att,
    const float* __restrict__ b_att) {
  extern __shared__ float dyns[];
  float* sD = dyns;                    // 68*256
  float* sm_sc = dyns + 68 * 256;      // 256 (compacted logits)
  float* spc = sm_sc + 256;            // 256 (compacted probs)
  float* sm_red = spc + 256;           // 32
  float* sm_agg = sm_red + 32;         // 768 (12 parts x 64)
  int* sj = (int*)(sm_agg + 768);      // 256
  float* st2 = (float*)(sj + 256);     // 256
  int* swcnt = (int*)(st2 + 256);      // 8
  int* sbase = swcnt + 8;              // 9
  float* ss1 = (float*)(sbase + 9);    // 8

  int b = blockIdx.x, il = blockIdx.y;
  int slot = b * 8 + il;
  int tid = threadIdx.x;
  int w = tid >> 5, lane = tid & 31;

  int start = asp_s[b], endi = asp_e[b];
  int i = start + il;
  bool active = (i <= endi) && (i < Sdim);
  const int* deprow = deprel + (size_t)(b * Sdim + (active ? i : 0)) * Sdim;

  int flag = 0;
  if (active && tid < Sdim) flag = (deprow[tid] > 0) ? 1 : 0;
  int any = __syncthreads_or(flag);
  if (!active || !any) {
    if (tid < H4) {
      float4 z = make_float4(0.f, 0.f, 0.f, 0.f);
      ((float4*)g_X1)[slot * H4 + tid] = z;
      ((float4*)g_X1)[(NSLOT + slot) * H4 + tid] = z;
    }
    if (tid < Ddim) g_X2[slot * (Hdim + Ddim) + Hdim + tid] = 0.f;
    if (tid == 0) {
      g_valid[slot] = 0;
      g_rowi[slot] = 0;
    }
    return;
  }

  // ballot-compact unmasked j (warps 0..7 cover j=0..255)
  unsigned bmask = 0;
  if (tid < Sdim) {
    bmask = __ballot_sync(0xffffffffu, flag);
    if ((tid & 31) == 0) swcnt[tid >> 5] = __popc(bmask);
  }
  __syncthreads();
  if (tid == 0) {
    int acc = 0;
#pragma unroll
    for (int ww = 0; ww < 8; ++ww) {
      sbase[ww] = acc;
      acc += swcnt[ww];
    }
    sbase[8] = acc;
  }
  __syncthreads();
  int cnt = sbase[8];
  if (tid < Sdim && flag) {
    int pos = sbase[tid >> 5] + __popc(bmask & ((1u << (tid & 31)) - 1u));
    sj[pos] = tid;
  }
  __syncthreads();

  // stage only compacted dta rows (16 float4 each)
  const float4* drow4 = (const float4*)(dta + (size_t)(b * Sdim + i) * Sdim * Ddim);
  for (int t = tid; t < cnt * 16; t += 1024) {
    int c = t >> 4, q = t & 15;
    cpasync16(saddr_of(sD + c * 68 + q * 4), drow4 + sj[c] * 16 + q);
  }
  cpasync_commit();

  int inext = (i + 1) & (Sdim - 1);
  const float* bi = bert + (size_t)(b * Sdim + inext) * Hdim;

  // bert_next row -> X1[128+slot]
  if (tid < H4)
    ((float4*)g_X1)[(NSLOT + slot) * H4 + tid] = ((const float4*)bi)[tid];

  // PARALLEL: warps 0-23 -> t2 dots for compacted rows; warps 24-31 -> s1.
  if (w < 24) {
    const float4* u24 = (const float4*)g_u2;
    for (int c = w; c < cnt; c += 24) {
      int j1 = (sj[c] + 1) & (Sdim - 1);
      const float4* br = (const float4*)(bert + (size_t)(b * Sdim + j1) * Hdim);
      float a2 = 0.f;
#pragma unroll
      for (int k = lane; k < H4; k += 32) {
        float4 bv = br[k];
        float4 uv = u24[k];
        a2 = fmaf(bv.x, uv.x, a2);
        a2 = fmaf(bv.y, uv.y, a2);
        a2 = fmaf(bv.z, uv.z, a2);
        a2 = fmaf(bv.w, uv.w, a2);
      }
      a2 = warpReduceSum(a2);
      if (lane == 0) st2[c] = a2 + g_c[1];
    }
  } else {
    int t = tid - 768;  // 0..255
    float a = bi[t] * g_u1[t] + bi[t + 256] * g_u1[t + 256] +
              bi[t + 512] * g_u1[t + 512];
    a = warpReduceSum(a);
    if (lane == 0) ss1[w - 24] = a;
  }
  cpasync_wait0();
  __syncthreads();

  float s1 = ss1[0] + ss1[1] + ss1[2] + ss1[3] + ss1[4] + ss1[5] + ss1[6] + ss1[7];
  float base = s1 + g_c[0] + b_att[0];

  // logits for compacted c: 4 threads per c
  {
    int c = tid >> 2, q = tid & 3;
    float acc = 0.f;
    if (c < cnt) {
      const float4* dj = (const float4*)(sD + c * 68) + q * 4;
      const float4* w34 = (const float4*)(w_att + 2 * Hdim) + q * 4;
#pragma unroll
      for (int k = 0; k < 4; ++k) {
        float4 d = dj[k];
        float4 ww = w34[k];
        acc = fmaf(d.x, ww.x, acc);
        acc = fmaf(d.y, ww.y, acc);
        acc = fmaf(d.z, ww.z, acc);
        acc = fmaf(d.w, ww.w, acc);
      }
    }
    acc += __shfl_xor_sync(0xffffffffu, acc, 1);
    acc += __shfl_xor_sync(0xffffffffu, acc, 2);
    if (c < cnt && q == 0) {
      float s = base + st2[c] + acc;
      s = (s >= 0.f) ? s : 0.01f * s;
      sm_sc[c] = s;
    }
  }
  __syncthreads();

  // softmax over compacted list (identical to full: masked terms are exactly 0)
  float sv = (tid < cnt) ? sm_sc[tid] : -1e30f;
  float m = blockReduceMax32(sv, sm_red);
  float e = (tid < cnt) ? expf(sv - m) : 0.f;
  float sum = blockReduceSum32(e, sm_red);
  if (tid < cnt) spc[tid] = e / sum;
  __syncthreads();

  // PARALLEL: v (threads 0-191, L1-hot bert rows) || agg_d (threads 256-1023)
  if (tid < H4) {
    const float4* bb4 = (const float4*)(bert + (size_t)b * Sdim * Hdim);
    float4 acc = make_float4(0.f, 0.f, 0.f, 0.f);
    for (int c = 0; c < cnt; ++c) {
      float p = spc[c];
      int j1 = (sj[c] + 1) & (Sdim - 1);
      float4 bv = bb4[(size_t)j1 * H4 + tid];
      acc.x = fmaf(p, bv.x, acc.x);
      acc.y = fmaf(p, bv.y, acc.y);
      acc.z = fmaf(p, bv.z, acc.z);
      acc.w = fmaf(p, bv.w, acc.w);
    }
    ((float4*)g_X1)[slot * H4 + tid] = acc;
  } else if (tid >= 256) {
    int d = tid & 63, part = (tid - 256) >> 6;  // 0..11
    float ad = 0.f;
    for (int c = part; c < cnt; c += 12) ad = fmaf(spc[c], sD[c * 68 + d], ad);
    sm_agg[part * 64 + d] = ad;
  }
  __syncthreads();
  if (tid < Ddim) {
    float t = 0.f;
#pragma unroll
    for (int p = 0; p < 12; ++p) t += sm_agg[p * 64 + tid];
    g_X2[slot * (Hdim + Ddim) + Hdim + tid] = t;
  }
  if (tid == 0) {
    g_valid[slot] = 1;
    g_rowi[slot] = i;
  }
}

#define FMAK4(C, WV, A0, A1, A2, A3)  \
  do {                                \
    unsigned long long s;             \
    s = splat2(x0.C);                 \
    ffma2(A0##l, s, (WV).x);          \
    ffma2(A0##h, s, (WV).y);          \
    s = splat2(x1.C);                 \
    ffma2(A1##l, s, (WV).x);          \
    ffma2(A1##h, s, (WV).y);          \
    s = splat2(x2.C);                 \
    ffma2(A2##l, s, (WV).x);          \
    ffma2(A2##h, s, (WV).y);          \
    s = splat2(x3.C);                 \
    ffma2(A3##l, s, (WV).x);          \
    ffma2(A3##h, s, (WV).y);          \
  } while (0)

// cp.async smem-staged K-split partial GEMM. 128 threads = 16 ct x 8 rt ->
// tile 64 cols x 64 rows (4 cols x 8 rows per thread). Small smem (33KB) ->
// ~6 blocks/SM. grid = (12, rows/64, ksplit).
template <int KS, int LDX, int NIT, int NROWS>
__global__ void __launch_bounds__(128) k_sgemm(const float* __restrict__ X,
                                               const float* __restrict__ W,
                                               float* __restrict__ P) {
  static_assert(KS == NIT * 32, "");
  __shared__ __align__(16) float sW[2][32 * 64];  // 16 KB
  __shared__ __align__(16) float sX[2][64 * 32];  // 16 KB

  int tid = threadIdx.x;
  int ct = tid & 15, rt = tid >> 4;
  int hb = blockIdx.x * 64;
  int rb = blockIdx.y * 64;
  int z = blockIdx.z;

  const float* Wg = W + (size_t)z * KS * Hdim + hb;
  const float* Xg = X + (size_t)rb * LDX + (size_t)z * KS;

  // Loaders (128 threads): W tile 32x64 = 512 float4 (4/thread);
  // X tile 64x32 = 512 float4 (4/thread).
  int wi = tid >> 4, wj = (tid & 15) * 4;  // W rows wi, wi+8, wi+16, wi+24
  int xi = tid >> 3, xj = (tid & 7) * 4;   // X rows xi, xi+16, xi+32, xi+48
  unsigned int sw0 = saddr_of(&sW[0][0]);
  unsigned int sx0 = saddr_of(&sX[0][0]);

#define LOAD_STAGE(stage, buf)                                                  \
  do {                                                                          \
    int k0 = (stage) * 32;                                                      \
    unsigned int swb = sw0 + (buf) * (32 * 64 * 4);                             \
    unsigned int sxb = sx0 + (buf) * (64 * 32 * 4);                             \
    cpasync16(swb + (wi * 64 + wj) * 4, Wg + (size_t)(k0 + wi) * Hdim + wj);    \
    cpasync16(swb + ((wi + 8) * 64 + wj) * 4,                                   \
              Wg + (size_t)(k0 + wi + 8) * Hdim + wj);                          \
    cpasync16(swb + ((wi + 16) * 64 + wj) * 4,                                  \
              Wg + (size_t)(k0 + wi + 16) * Hdim + wj);                         \
    cpasync16(swb + ((wi + 24) * 64 + wj) * 4,                                  \
              Wg + (size_t)(k0 + wi + 24) * Hdim + wj);                         \
    cpasync16(sxb + (xi * 32 + xj) * 4, Xg + (size_t)xi * LDX + k0 + xj);       \
    cpasync16(sxb + ((xi + 16) * 32 + xj) * 4,                                  \
              Xg + (size_t)(xi + 16) * LDX + k0 + xj);                          \
    cpasync16(sxb + ((xi + 32) * 32 + xj) * 4,                                  \
              Xg + (size_t)(xi + 32) * LDX + k0 + xj);                          \
    cpasync16(sxb + ((xi + 48) * 32 + xj) * 4,                                  \
              Xg + (size_t)(xi + 48) * LDX + k0 + xj);                          \
    cpasync_commit();                                                           \
  } while (0)

  LOAD_STAGE(0, 0);
  if (NIT > 1) LOAD_STAGE(1, 1);

  unsigned long long a0l = 0, a0h = 0, a1l = 0, a1h = 0;
  unsigned long long a2l = 0, a2h = 0, a3l = 0, a3h = 0;
  unsigned long long a4l = 0, a4h = 0, a5l = 0, a5h = 0;
  unsigned long long a6l = 0, a6h = 0, a7l = 0, a7h = 0;
  int r0 = rt * 8;

#pragma unroll 1
  for (int it = 0; it < NIT; ++it) {
    if (it < NIT - 1)
      cpasync_wait1();
    else
      cpasync_wait0();
    __syncthreads();
    int buf = it & 1;
    const float* xbase = &sX[buf][0];
    const float* wb = &sW[buf][ct * 4];
#pragma unroll
    for (int k4 = 0; k4 < 8; ++k4) {
      ulonglong2 w0 = *(const ulonglong2*)(wb + (k4 * 4 + 0) * 64);
      ulonglong2 w1 = *(const ulonglong2*)(wb + (k4 * 4 + 1) * 64);
      ulonglong2 w2 = *(const ulonglong2*)(wb + (k4 * 4 + 2) * 64);
      ulonglong2 w3 = *(const ulonglong2*)(wb + (k4 * 4 + 3) * 64);
      {
        float4 x0 = *(const float4*)(xbase + (r0 + 0) * 32 + k4 * 4);
        float4 x1 = *(const float4*)(xbase + (r0 + 1) * 32 + k4 * 4);
        float4 x2 = *(const float4*)(xbase + (r0 + 2) * 32 + k4 * 4);
        float4 x3 = *(const float4*)(xbase + (r0 + 3) * 32 + k4 * 4);
        FMAK4(x, w0, a0, a1, a2, a3);
        FMAK4(y, w1, a0, a1, a2, a3);
        FMAK4(z, w2, a0, a1, a2, a3);
        FMAK4(w, w3, a0, a1, a2, a3);
      }
      {
        float4 x0 = *(const float4*)(xbase + (r0 + 4) * 32 + k4 * 4);
        float4 x1 = *(const float4*)(xbase + (r0 + 5) * 32 + k4 * 4);
        float4 x2 = *(const float4*)(xbase + (r0 + 6) * 32 + k4 * 4);
        float4 x3 = *(const float4*)(xbase + (r0 + 7) * 32 + k4 * 4);
        FMAK4(x, w0, a4, a5, a6, a7);
        FMAK4(y, w1, a4, a5, a6, a7);
        FMAK4(z, w2, a4, a5, a6, a7);
        FMAK4(w, w3, a4, a5, a6, a7);
      }
    }
    __syncthreads();
    if (it + 2 < NIT) LOAD_STAGE(it + 2, buf);
  }
#undef LOAD_STAGE

  int r = rb + r0;
  float* pr = P + ((size_t)(z * NROWS + r)) * Hdim + hb + ct * 4;
#define STORE_ROW(q, A)                                                  \
  {                                                                      \
    float2 fl = u2f(A##l), fh = u2f(A##h);                               \
    *(float4*)(pr + (q)*Hdim) = make_float4(fl.x, fl.y, fh.x, fh.y);     \
  }
  STORE_ROW(0, a0)
  STORE_ROW(1, a1)
  STORE_ROW(2, a2)
  STORE_ROW(3, a3)
  STORE_ROW(4, a4)
  STORE_ROW(5, a5)
  STORE_ROW(6, a6)
  STORE_ROW(7, a7)
#undef STORE_ROW
}

// Epilogue: combine NZ K-split partials at OFF and route per MODE. block 192.
template <int NZ, int OFF, int NROWS, int MODE>
__global__ void __launch_bounds__(192) k_epi(const float* __restrict__ bias,
                                             float* __restrict__ outp) {
  int r = blockIdx.x;
  if (MODE == 2 && !g_valid[r]) return;
  int h = threadIdx.x * 4;
  float4 v = make_float4(0.f, 0.f, 0.f, 0.f);
#pragma unroll
  for (int zz = 0; zz < NZ; ++zz) {
    const float4 p =
        *(const float4*)(g_P + (size_t)(OFF + zz * NROWS + r) * Hdim + h);
    v.x += p.x;
    v.y += p.y;
    v.z += p.z;
    v.w += p.w;
  }
  if (MODE == 0) {
    const float4 bb = *(const float4*)(bias + h);
    v.x += bb.x;
    v.y += bb.y;
    v.z += bb.z;
    v.w += bb.w;
    if (r < NSLOT)
      *(float4*)(g_X2 + (size_t)r * (Hdim + Ddim) + h) = v;
    else
      *(float4*)(g_X3 + (size_t)(r - NSLOT) * (2 * Hdim) + Hdim + h) = v;
  } else if (MODE == 1) {
    *(float4*)(g_X3 + (size_t)r * (2 * Hdim) + h) = v;
  } else {
    int bb = r >> 3;
    int o = (g_rowi[r] + 1) & (Sdim - 1);
    *(float4*)(outp + ((size_t)(bb * Sdim + o)) * Hdim + h) = v;
  }
}

extern "C" void kernel_launch(void* const* d_in, const int* in_sizes, int n_in,
                              void* d_out, int out_size) {
  const float* bert = (const float*)d_in[0];
  const float* dta = (const float*)d_in[1];
  const int* deprel = (const int*)d_in[2];
  const int* asp_s = (const int*)d_in[3];
  const int* asp_e = (const int*)d_in[4];
  const float* Wz = (const float*)d_in[5];
  const float* bz = (const float*)d_in[6];
  const float* watt = (const float*)d_in[7];
  const float* batt = (const float*)d_in[8];
  const float* Wf = (const float*)d_in[9];
  const float* Wh = (const float*)d_in[10];
  float* out = (float*)d_out;

  float* P;
  float* X1;
  float* X2;
  float* X3;
  cudaGetSymbolAddress((void**)&P, g_P);
  cudaGetSymbolAddress((void**)&X1, g_X1);
  cudaGetSymbolAddress((void**)&X2, g_X2);
  cudaGetSymbolAddress((void**)&X3, g_X3);

  // Fork: bulk copy on s3; sparse L2 prefetch on s2.
  cudaEventRecord(g_evFork, 0);
  cudaStreamWaitEvent(g_s3, g_evFork, 0);
  cudaStreamWaitEvent(g_s2, g_evFork, 0);
  k_copy<<<(Bdim * Sdim * Hdim / 4) / 256, 256, 0, g_s3>>>((const float4*)bert,
                                                           (float4*)out);
  cudaEventRecord(g_evCopy, g_s3);
  k_pref<<<NSLOT, 256, 0, g_s2>>>(dta, deprel, asp_s, asp_e);
  cudaEventRecord(g_evPref, g_s2);

  // Critical path.
  k_pre<<<769, 256>>>(Wz, bz, watt);
  k_att<<<dim3(Bdim, 8), 1024, ATT_SMEM_FLOATS * 4>>>(bert, dta, deprel, asp_s,
                                                      asp_e, watt, batt);
  // gemm0: X1(256 x 768) @ Wz   K=768 z=12 -> P0, epi adds bz
  k_sgemm<64, Hdim, 2, 256><<<dim3(12, 4, 12), 128>>>(X1, Wz, P + (size_t)P0_OFF * Hdim);
  k_epi<12, P0_OFF, 256, 0><<<256, 192>>>(bz, nullptr);
  // gemm1: X2(128 x 832) @ Wf   K=832 z=13 -> P1 -> nrep
  k_sgemm<64, Hdim + Ddim, 2, 128><<<dim3(12, 2, 13), 128>>>(X2, Wf,
                                                             P + (size_t)P1_OFF * Hdim);
  k_epi<13, P1_OFF, 128, 1><<<128, 192>>>(nullptr, nullptr);
  // gemm2: X3(128 x 1536) @ Wh  K=1536 z=24 -> P2 -> out scatter
  k_sgemm<64, 2 * Hdim, 2, 128><<<dim3(12, 2, 24), 128>>>(X3, Wh,
                                                          P + (size_t)P2_OFF * Hdim);
  // Join copy + prefetch streams, then scatter.
  cudaStreamWaitEvent(0, g_evCopy, 0);
  cudaStreamWaitEvent(0, g_evPref, 0);
  k_epi<24, P2_OFF, 128, 2><<<128, 192>>>(nullptr, out);
}